// round 11
// baseline (speedup 1.0000x reference)
#include <cuda_runtime.h>

#define Bz  256
#define THz 512
#define TAz 576
#define Pz  16
#define Dz  512
#define Lz  128
#define Hz  256

// ---------------- scratch (static device globals; no allocation) ----------------
__device__ float g_x_hist[Bz*THz*Dz];          // [B,TH,D]
__device__ float g_x_all [Bz*TAz*Dz];          // [B,TA,D]; reused later as gelu output [B,TH,D]
__device__ float g_xgf   [Bz*TAz*4*Hz];        // [B,TA,4H]; reused later as cat [B,TH,D+L]
__device__ float g_xgb   [Bz*TAz*4*Hz];
__device__ float g_xgg   [Bz*THz*3*Dz];        // [B,TH,3D]
__device__ float g_hbi   [Bz*TAz*Dz];          // [B,TA,2H] (hf | hb)
__device__ float g_w2h   [Dz+1];               // W_e2@W_head, plus scalar c2 at [Dz]
__device__ unsigned g_bar;

// ---------------- helpers ----------------
__device__ __forceinline__ float sigf(float x){ return 1.f/(1.f+expf(-x)); }

__device__ __forceinline__ float act_apply(float v, int act){
  if (act == 1){                      // softplus + 1e-5 (stable logaddexp(x,0))
    v = fmaxf(v, 0.f) + log1pf(expf(-fabsf(v))) + 1e-5f;
  } else if (act == 2){               // exact GELU
    v = 0.5f*v*(1.f + erff(v*0.7071067811865476f));
  }
  return v;
}

// Grid barrier across the 128 persistent blocks. Bounded spin: if co-residency
// ever fails, we bail out after ~20s instead of hanging the container (output
// then fails rel_err visibly).
__device__ __forceinline__ void gridsync(unsigned target){
  __threadfence();
  __syncthreads();
  if (threadIdx.x == 0){
    atomicAdd(&g_bar, 1u);
    long long start = clock64();
    unsigned v;
    do {
      asm volatile("ld.global.cg.u32 %0, [%1];" : "=r"(v) : "l"(&g_bar));
      if (v >= target) break;
      __nanosleep(64);
    } while (clock64() - start < 40000000000LL);
    __threadfence();
  }
  __syncthreads();
}

__global__ void reset_bar_kernel(){ g_bar = 0u; }

// ---------------- embed: X = patches @ W_embed + b ----------------
__global__ __launch_bounds__(256) void embed_kernel(
    const float* __restrict__ patches, const float* __restrict__ W,
    const float* __restrict__ bias, float* __restrict__ X)
{
  __shared__ float sW[Pz*Dz];
  __shared__ float sb[Dz];
  __shared__ float sP[64*Pz];
  int tid = threadIdx.x;
  for (int i = tid; i < Pz*Dz; i += 256) sW[i] = W[i];
  for (int i = tid; i < Dz;    i += 256) sb[i] = bias[i];
  size_t r0 = (size_t)blockIdx.x * 64;
  for (int i = tid; i < 64*Pz; i += 256) sP[i] = patches[r0*Pz + i];
  __syncthreads();
  for (int rr = 0; rr < 64; rr++){
    const float* pv = sP + rr*Pz;
    #pragma unroll
    for (int half = 0; half < 2; half++){
      int d = tid + half*256;
      float acc = sb[d];
      #pragma unroll
      for (int p = 0; p < Pz; p++) acc += pv[p]*sW[p*Dz + d];
      X[(r0+rr)*Dz + d] = acc;
    }
  }
}

// ---------------- generic SGEMM: C[M,N] = A[M,K] @ W[K,N] + bias, act ----------------
// grid (N/128, M/128), 256 threads, 128x128x16 tiles, 8x8 microtile.
__global__ __launch_bounds__(256) void sgemm_kernel(
    const float* __restrict__ A, const float* __restrict__ W,
    const float* __restrict__ bias, float* __restrict__ C,
    int M, int N, int K, int act)
{
  __shared__ float sA[16][132];
  __shared__ float sB[16][128];
  int tid = threadIdx.x;
  int bm = blockIdx.y*128, bn = blockIdx.x*128;
  int tx = tid & 15, ty = tid >> 4;
  int arow = tid >> 2,  acol = (tid & 3)*4;
  int brow = tid >> 5,  bcol = (tid & 31)*4;
  const float* Ap  = A + (size_t)(bm + arow)*K + acol;
  const float* Ap2 = Ap + (size_t)64*K;
  const float* Wp  = W + (size_t)brow*N + bn + bcol;
  const float* Wp2 = Wp + (size_t)8*N;

  float acc[8][8];
  #pragma unroll
  for (int i = 0; i < 8; i++)
    #pragma unroll
    for (int j = 0; j < 8; j++) acc[i][j] = 0.f;

  for (int kk = 0; kk < K; kk += 16){
    float4 a0 = *(const float4*)Ap;
    float4 a1 = *(const float4*)Ap2;
    float4 b0 = *(const float4*)Wp;
    float4 b1 = *(const float4*)Wp2;
    Ap += 16; Ap2 += 16;
    Wp += (size_t)16*N; Wp2 += (size_t)16*N;
    sA[acol+0][arow] = a0.x; sA[acol+1][arow] = a0.y;
    sA[acol+2][arow] = a0.z; sA[acol+3][arow] = a0.w;
    sA[acol+0][arow+64] = a1.x; sA[acol+1][arow+64] = a1.y;
    sA[acol+2][arow+64] = a1.z; sA[acol+3][arow+64] = a1.w;
    *(float4*)&sB[brow  ][bcol] = b0;
    *(float4*)&sB[brow+8][bcol] = b1;
    __syncthreads();
    #pragma unroll
    for (int k = 0; k < 16; k++){
      float af[8], bf[8];
      *(float4*)&af[0] = *(const float4*)&sA[k][ty*8];
      *(float4*)&af[4] = *(const float4*)&sA[k][ty*8+4];
      *(float4*)&bf[0] = *(const float4*)&sB[k][tx*8];
      *(float4*)&bf[4] = *(const float4*)&sB[k][tx*8+4];
      #pragma unroll
      for (int i = 0; i < 8; i++)
        #pragma unroll
        for (int j = 0; j < 8; j++)
          acc[i][j] += af[i]*bf[j];
    }
    __syncthreads();
  }

  #pragma unroll
  for (int i = 0; i < 8; i++){
    size_t row = (size_t)bm + ty*8 + i;
    float* Cr = C + row*N + bn + tx*8;
    #pragma unroll
    for (int j = 0; j < 8; j++){
      float v = acc[i][j] + bias[bn + tx*8 + j];
      Cr[j] = act_apply(v, act);
    }
  }
}

// ---------------- persistent bi-LSTM (time loop inside; grid barrier per step) ----
// 128 blocks: dir(2) x btile(8) x jtile(8). Tile = 32 batch rows x 32 hidden cols, all 4 gates.
__global__ __launch_bounds__(256) void lstm_kernel(
    const float* __restrict__ xgf, const float* __restrict__ xgb,
    const float* __restrict__ Whh_f, const float* __restrict__ Whh_b,
    const float* __restrict__ bhh_f, const float* __restrict__ bhh_b,
    float* __restrict__ hbi)
{
  __shared__ float sA[32][32];
  __shared__ float sB[4][32][33];
  int tid = threadIdx.x, blk = blockIdx.x;
  int dir = blk >> 6;
  int bt  = (blk >> 3) & 7;
  int jt  = blk & 7;
  int b0 = bt*32, j0 = jt*32;
  const float* xg  = dir ? xgb   : xgf;
  const float* Whh = dir ? Whh_b : Whh_f;
  const float* bhh = dir ? bhh_b : bhh_f;
  int tx = tid & 31, ty = tid >> 5;    // ty 0..7, 4 batch rows each

  float bh[4];
  #pragma unroll
  for (int g = 0; g < 4; g++) bh[g] = bhh[g*Hz + j0 + tx];

  float c_reg[4] = {0.f,0.f,0.f,0.f};
  unsigned target = 0;

  for (int t = 0; t < TAz; t++){
    int te = dir ? (TAz-1-t) : t;
    float acc[4][4] = {{0,0,0,0},{0,0,0,0},{0,0,0,0},{0,0,0,0}};
    if (t > 0){
      int tp = dir ? te+1 : te-1;
      for (int kk = 0; kk < Hz; kk += 32){
        #pragma unroll
        for (int i = 0; i < 4; i++){
          int idx = tid + i*256;
          int r = idx >> 5, c = idx & 31;
          sA[r][c] = __ldcg(&hbi[((size_t)(b0+r)*TAz + tp)*512 + dir*Hz + kk + c]);
        }
        #pragma unroll
        for (int i = 0; i < 16; i++){
          int idx = tid + i*256;
          int g = idx >> 10, rem = idx & 1023;
          int k = rem >> 5, j = rem & 31;
          sB[g][k][j] = Whh[(kk + k)*(4*Hz) + g*Hz + j0 + j];
        }
        __syncthreads();
        #pragma unroll
        for (int k = 0; k < 32; k++){
          float bg0 = sB[0][k][tx], bg1 = sB[1][k][tx];
          float bg2 = sB[2][k][tx], bg3 = sB[3][k][tx];
          #pragma unroll
          for (int rr = 0; rr < 4; rr++){
            float a = sA[ty*4+rr][k];
            acc[0][rr] += a*bg0; acc[1][rr] += a*bg1;
            acc[2][rr] += a*bg2; acc[3][rr] += a*bg3;
          }
        }
        __syncthreads();
      }
    }
    #pragma unroll
    for (int rr = 0; rr < 4; rr++){
      int b = b0 + ty*4 + rr;
      size_t base = ((size_t)b*TAz + te)*(4*Hz) + j0 + tx;
      float gi = acc[0][rr] + xg[base + 0*Hz] + bh[0];
      float gf = acc[1][rr] + xg[base + 1*Hz] + bh[1];
      float gg = acc[2][rr] + xg[base + 2*Hz] + bh[2];
      float go = acc[3][rr] + xg[base + 3*Hz] + bh[3];
      float c = sigf(gf)*c_reg[rr] + sigf(gi)*tanhf(gg);
      c_reg[rr] = c;
      hbi[((size_t)b*TAz + te)*512 + dir*Hz + j0 + tx] = sigf(go)*tanhf(c);
    }
    target += 128u;
    gridsync(target);
  }
}

// ---------------- persistent GRU ----------------
// 128 blocks: btile(8) x jtile(16). Tile = 32 x 32, 3 gates. Writes h_seq to d_out region.
__global__ __launch_bounds__(256) void gru_kernel(
    const float* __restrict__ xgg, const float* __restrict__ Whh,
    const float* __restrict__ bhh, float* __restrict__ h_out)
{
  __shared__ float sA[32][32];
  __shared__ float sB[3][32][33];
  int tid = threadIdx.x, blk = blockIdx.x;
  int bt = blk >> 4, jt = blk & 15;
  int b0 = bt*32, j0 = jt*32;
  int tx = tid & 31, ty = tid >> 5;

  float bh[3];
  #pragma unroll
  for (int g = 0; g < 3; g++) bh[g] = bhh[g*Dz + j0 + tx];

  unsigned target = 0;
  for (int t = 0; t < THz; t++){
    float acc[3][4] = {{0,0,0,0},{0,0,0,0},{0,0,0,0}};
    if (t > 0){
      for (int kk = 0; kk < Dz; kk += 32){
        #pragma unroll
        for (int i = 0; i < 4; i++){
          int idx = tid + i*256;
          int r = idx >> 5, c = idx & 31;
          sA[r][c] = __ldcg(&h_out[((size_t)(b0+r)*THz + (t-1))*Dz + kk + c]);
        }
        #pragma unroll
        for (int i = 0; i < 12; i++){
          int idx = tid + i*256;
          int g = idx >> 10, rem = idx & 1023;
          int k = rem >> 5, j = rem & 31;
          sB[g][k][j] = Whh[(kk + k)*(3*Dz) + g*Dz + j0 + j];
        }
        __syncthreads();
        #pragma unroll
        for (int k = 0; k < 32; k++){
          float bg0 = sB[0][k][tx], bg1 = sB[1][k][tx], bg2 = sB[2][k][tx];
          #pragma unroll
          for (int rr = 0; rr < 4; rr++){
            float a = sA[ty*4+rr][k];
            acc[0][rr] += a*bg0; acc[1][rr] += a*bg1; acc[2][rr] += a*bg2;
          }
        }
        __syncthreads();
      }
    }
    #pragma unroll
    for (int rr = 0; rr < 4; rr++){
      int b = b0 + ty*4 + rr;
      size_t xbase = ((size_t)b*THz + t)*(3*Dz) + j0 + tx;
      float xr = xgg[xbase + 0*Dz], xz = xgg[xbase + 1*Dz], xn = xgg[xbase + 2*Dz];
      float r = sigf(xr + acc[0][rr] + bh[0]);
      float z = sigf(xz + acc[1][rr] + bh[1]);
      float n = tanhf(xn + r*(acc[2][rr] + bh[2]));
      float hp = (t > 0) ? __ldcg(&h_out[((size_t)b*THz + (t-1))*Dz + j0 + tx]) : 0.f;
      h_out[((size_t)b*THz + t)*Dz + j0 + tx] = (1.f - z)*n + z*hp;
    }
    target += 128u;
    gridsync(target);
  }
}

// ---------------- fold W_e2 @ W_head into one vector + scalar ----------------
__global__ void w2h_kernel(const float* __restrict__ W_e2, const float* __restrict__ b_e2,
                           const float* __restrict__ W_head, const float* __restrict__ b_head)
{
  int tid = threadIdx.x;
  for (int d = tid; d < Dz; d += 256){
    float s = 0.f;
    for (int j = 0; j < Dz; j++) s += W_e2[(size_t)d*Dz + j]*W_head[j];
    g_w2h[d] = s;
  }
  if (tid == 0){
    float s = 0.f;
    for (int j = 0; j < Dz; j++) s += b_e2[j]*W_head[j];
    g_w2h[Dz] = s + b_head[0];
  }
}

// ---------------- build cat = [h_seq, qm + qs*eps] ----------------
__global__ __launch_bounds__(256) void cat_kernel(
    const float* __restrict__ h, const float* __restrict__ qm,
    const float* __restrict__ qs, const float* __restrict__ eps,
    float* __restrict__ cat)
{
  int row = blockIdx.x;               // b*TH + t
  int tid = threadIdx.x;
  float* dst = cat + (size_t)row*(Dz+Lz);
  const float* hs = h + (size_t)row*Dz;
  for (int i = tid; i < Dz; i += 256) dst[i] = hs[i];
  int b = row >> 9, t = row & 511;
  size_t q = ((size_t)b*TAz + t)*Lz;
  size_t e = (size_t)row*Lz;
  for (int i = tid; i < Lz; i += 256) dst[Dz+i] = qm[q+i] + qs[q+i]*eps[e+i];
}

// ---------------- y = gelu_out @ w2h + c2 ----------------
__global__ __launch_bounds__(256) void y_kernel(const float* __restrict__ gel,
                                                float* __restrict__ out_y)
{
  __shared__ float sw[Dz];
  __shared__ float c2s;
  int tid = threadIdx.x;
  for (int i = tid; i < Dz; i += 256) sw[i] = g_w2h[i];
  if (tid == 0) c2s = g_w2h[Dz];
  __syncthreads();
  int lane = tid & 31;
  int warp = (blockIdx.x*blockDim.x + tid) >> 5;
  int nwarp = (gridDim.x*blockDim.x) >> 5;
  for (int row = warp; row < Bz*THz; row += nwarp){
    const float* g = gel + (size_t)row*Dz;
    float s = 0.f;
    #pragma unroll
    for (int i = 0; i < Dz/32; i++) s += g[lane + i*32]*sw[lane + i*32];
    #pragma unroll
    for (int o = 16; o; o >>= 1) s += __shfl_xor_sync(0xffffffffu, s, o);
    if (lane == 0) out_y[row] = s + c2s;
  }
}

// ---------------- launch ----------------
extern "C" void kernel_launch(void* const* d_in, const int* in_sizes, int n_in,
                              void* d_out, int out_size)
{
  (void)in_sizes; (void)n_in; (void)out_size;
  const float* patches_hist = (const float*)d_in[0];
  const float* patches_all  = (const float*)d_in[1];
  const float* eps    = (const float*)d_in[2];
  const float* W_embed= (const float*)d_in[3];
  const float* b_embed= (const float*)d_in[4];
  const float* Wih_f  = (const float*)d_in[5];
  const float* Whh_f  = (const float*)d_in[6];
  const float* bih_f  = (const float*)d_in[7];
  const float* bhh_f  = (const float*)d_in[8];
  const float* Wih_b  = (const float*)d_in[9];
  const float* Whh_b  = (const float*)d_in[10];
  const float* bih_b  = (const float*)d_in[11];
  const float* bhh_b  = (const float*)d_in[12];
  const float* Wqm    = (const float*)d_in[13];
  const float* bqm    = (const float*)d_in[14];
  const float* Wqs    = (const float*)d_in[15];
  const float* bqs    = (const float*)d_in[16];
  const float* Wih_g  = (const float*)d_in[17];
  const float* Whh_g  = (const float*)d_in[18];
  const float* bih_g  = (const float*)d_in[19];
  const float* bhh_g  = (const float*)d_in[20];
  const float* Wqm2   = 0; (void)Wqm2;
  const float* Wpm    = (const float*)d_in[21];
  const float* bpm    = (const float*)d_in[22];
  const float* Wps    = (const float*)d_in[23];
  const float* bps    = (const float*)d_in[24];
  const float* W_e1   = (const float*)d_in[25];
  const float* b_e1   = (const float*)d_in[26];
  const float* W_e2   = (const float*)d_in[27];
  const float* b_e2   = (const float*)d_in[28];
  const float* W_head = (const float*)d_in[29];
  const float* b_head = (const float*)d_in[30];
  float* out = (float*)d_out;

  // output layout: y_hist, prior_m, prior_s, qm_all, qs_all, h_seq (flattened, concatenated)
  float* out_y  = out + 0;
  float* out_pm = out + 131072;
  float* out_ps = out + 16908288;
  float* out_qm = out + 33685504;
  float* out_qs = out + 52559872;
  float* out_h  = out + 71434240;

  float *x_hist, *x_all, *xgf, *xgb, *xgg, *hbi;
  cudaGetSymbolAddress((void**)&x_hist, g_x_hist);
  cudaGetSymbolAddress((void**)&x_all,  g_x_all);
  cudaGetSymbolAddress((void**)&xgf,    g_xgf);
  cudaGetSymbolAddress((void**)&xgb,    g_xgb);
  cudaGetSymbolAddress((void**)&xgg,    g_xgg);
  cudaGetSymbolAddress((void**)&hbi,    g_hbi);
  float* cat = xgf;     // reuse: xgf dead after LSTM steps  (needs 83.9M <= 151M floats)
  float* gel = x_all;   // reuse: x_all dead after xg GEMMs  (needs 67.1M <= 75.5M floats)

  // 1. embed
  embed_kernel<<<(Bz*TAz)/64, 256>>>(patches_all,  W_embed, b_embed, x_all);
  embed_kernel<<<(Bz*THz)/64, 256>>>(patches_hist, W_embed, b_embed, x_hist);

  // 2. input-gate GEMMs
  sgemm_kernel<<<dim3(1024/128, (Bz*TAz)/128), 256>>>(x_all,  Wih_f, bih_f, xgf, Bz*TAz, 1024, 512, 0);
  sgemm_kernel<<<dim3(1024/128, (Bz*TAz)/128), 256>>>(x_all,  Wih_b, bih_b, xgb, Bz*TAz, 1024, 512, 0);
  sgemm_kernel<<<dim3(1536/128, (Bz*THz)/128), 256>>>(x_hist, Wih_g, bih_g, xgg, Bz*THz, 1536, 512, 0);

  // 3. recurrences: persistent kernels, software grid barrier (2 nodes instead of 1088)
  reset_bar_kernel<<<1,1>>>();
  lstm_kernel<<<128,256>>>(xgf, xgb, Whh_f, Whh_b, bhh_f, bhh_b, hbi);
  reset_bar_kernel<<<1,1>>>();
  gru_kernel<<<128,256>>>(xgg, Whh_g, bhh_g, out_h);

  // 4. posterior / prior heads
  sgemm_kernel<<<dim3(1, (Bz*TAz)/128), 256>>>(hbi,   Wqm, bqm, out_qm, Bz*TAz, 128, 512, 0);
  sgemm_kernel<<<dim3(1, (Bz*TAz)/128), 256>>>(hbi,   Wqs, bqs, out_qs, Bz*TAz, 128, 512, 1);
  sgemm_kernel<<<dim3(1, (Bz*THz)/128), 256>>>(out_h, Wpm, bpm, out_pm, Bz*THz, 128, 512, 0);
  sgemm_kernel<<<dim3(1, (Bz*THz)/128), 256>>>(out_h, Wps, bps, out_ps, Bz*THz, 128, 512, 1);

  // 5. emission (head folded: y = gelu(cat@W_e1+b_e1) @ (W_e2@W_head) + (b_e2@W_head + b_head))
  w2h_kernel<<<1,256>>>(W_e2, b_e2, W_head, b_head);
  cat_kernel<<<Bz*THz, 256>>>(out_h, out_qm, out_qs, eps, cat);
  sgemm_kernel<<<dim3(512/128, (Bz*THz)/128), 256>>>(cat, W_e1, b_e1, gel, Bz*THz, 512, 640, 2);
  y_kernel<<<2048,256>>>(gel, out_y);
}

// round 13
// speedup vs baseline: 1.3172x; 1.3172x over previous
#include <cuda_runtime.h>
#include <cstdint>

#define Bz  256
#define THz 512
#define TAz 576
#define Pz  16
#define Dz  512
#define Lz  128
#define Hz  256

// ---------------- scratch (static device globals; no allocation) ----------------
__device__ float g_x_hist[Bz*THz*Dz];          // [B,TH,D]
__device__ float g_x_all [Bz*TAz*Dz];          // [B,TA,D]; reused later as gelu output [B,TH,D]
__device__ float g_xgf   [Bz*TAz*4*Hz];        // [B,TA,4H]; reused later as cat [B,TH,D+L]
__device__ float g_xgb   [Bz*TAz*4*Hz];
__device__ float g_xgg   [Bz*THz*3*Dz];        // [B,TH,3D]
__device__ float g_hbi   [Bz*TAz*Dz];          // [B,TA,2H] (hf | hb)
__device__ float g_w2h   [Dz+1];               // W_e2@W_head, plus scalar c2 at [Dz]
__device__ unsigned g_bar;

// ---------------- helpers ----------------
__device__ __forceinline__ float sigf(float x){ return 1.f/(1.f+expf(-x)); }

__device__ __forceinline__ float act_apply(float v, int act){
  if (act == 1){                      // softplus + 1e-5 (stable logaddexp(x,0))
    v = fmaxf(v, 0.f) + log1pf(expf(-fabsf(v))) + 1e-5f;
  } else if (act == 2){               // exact GELU
    v = 0.5f*v*(1.f + erff(v*0.7071067811865476f));
  }
  return v;
}

__device__ __forceinline__ uint32_t f2tf32(float f){
  uint32_t u; asm("cvt.rna.tf32.f32 %0, %1;" : "=r"(u) : "f"(f)); return u;
}

// m16n8k8 tf32 MMA (legacy tensor path; plain-PTX, works on sm_103 target)
__device__ __forceinline__ void mma_tf32(float* c, const uint32_t* a, uint32_t b0, uint32_t b1){
  asm volatile("mma.sync.aligned.m16n8k8.row.col.f32.tf32.tf32.f32 "
      "{%0,%1,%2,%3}, {%4,%5,%6,%7}, {%8,%9}, {%0,%1,%2,%3};"
      : "+f"(c[0]), "+f"(c[1]), "+f"(c[2]), "+f"(c[3])
      : "r"(a[0]), "r"(a[1]), "r"(a[2]), "r"(a[3]), "r"(b0), "r"(b1));
}

__device__ __forceinline__ void gridsync(unsigned target){
  __threadfence();
  __syncthreads();
  if (threadIdx.x == 0){
    atomicAdd(&g_bar, 1u);
    long long start = clock64();
    unsigned v;
    do {
      asm volatile("ld.global.cg.u32 %0, [%1];" : "=r"(v) : "l"(&g_bar));
      if (v >= target) break;
      __nanosleep(64);
    } while (clock64() - start < 40000000000LL);
    __threadfence();
  }
  __syncthreads();
}

__global__ void reset_bar_kernel(){ g_bar = 0u; }

// ---------------- embed: X = patches @ W_embed + b ----------------
__global__ __launch_bounds__(256) void embed_kernel(
    const float* __restrict__ patches, const float* __restrict__ W,
    const float* __restrict__ bias, float* __restrict__ X)
{
  __shared__ float sW[Pz*Dz];
  __shared__ float sb[Dz];
  __shared__ float sP[64*Pz];
  int tid = threadIdx.x;
  for (int i = tid; i < Pz*Dz; i += 256) sW[i] = W[i];
  for (int i = tid; i < Dz;    i += 256) sb[i] = bias[i];
  size_t r0 = (size_t)blockIdx.x * 64;
  for (int i = tid; i < 64*Pz; i += 256) sP[i] = patches[r0*Pz + i];
  __syncthreads();
  for (int rr = 0; rr < 64; rr++){
    const float* pv = sP + rr*Pz;
    #pragma unroll
    for (int half = 0; half < 2; half++){
      int d = tid + half*256;
      float acc = sb[d];
      #pragma unroll
      for (int p = 0; p < Pz; p++) acc += pv[p]*sW[p*Dz + d];
      X[(r0+rr)*Dz + d] = acc;
    }
  }
}

// ---------------- tf32 mma.sync GEMM: C[M,N] = A[M,K] @ W[K,N] + bias, act ----------
// grid (N/128, M/128), 256 threads = 8 warps (4 m x 2 n), warp tile 32x64,
// atoms m16n8k8, BK=32. A staged transposed [k][m] (stride 133), B natural [k][n].
#define SA_STRIDE 133
__global__ __launch_bounds__(256) void tgemm_kernel(
    const float* __restrict__ A, const float* __restrict__ W,
    const float* __restrict__ bias, float* __restrict__ C,
    int M, int N, int K, int act)
{
  __shared__ uint32_t sA[32*SA_STRIDE];  // [k][m]
  __shared__ uint32_t sB[32*132];        // [k][n]
  int tid = threadIdx.x;
  int lane = tid & 31, warp = tid >> 5;
  int wm = warp & 3, wn = warp >> 2;
  int gid = lane >> 2, tidg = lane & 3;
  int bm = blockIdx.y*128, bn = blockIdx.x*128;

  float acc[16][4];
  #pragma unroll
  for (int i = 0; i < 16; i++)
    #pragma unroll
    for (int j = 0; j < 4; j++) acc[i][j] = 0.f;

  for (int kk = 0; kk < K; kk += 32){
    // stage A (transpose + tf32 convert): 128x32 floats, 4 float4 per thread
    #pragma unroll
    for (int i = 0; i < 4; i++){
      int linear = tid + i*256;          // 0..1023
      int r  = linear >> 3;              // 0..127
      int c4 = linear & 7;               // 0..7
      float4 v = *(const float4*)(A + (size_t)(bm + r)*K + kk + c4*4);
      sA[(c4*4+0)*SA_STRIDE + r] = f2tf32(v.x);
      sA[(c4*4+1)*SA_STRIDE + r] = f2tf32(v.y);
      sA[(c4*4+2)*SA_STRIDE + r] = f2tf32(v.z);
      sA[(c4*4+3)*SA_STRIDE + r] = f2tf32(v.w);
    }
    // stage B: [k][n], coalesced float4
    #pragma unroll
    for (int i = 0; i < 4; i++){
      int linear = tid + i*256;
      int k  = linear >> 5;              // 0..31
      int n4 = linear & 31;              // 0..31
      float4 v = *(const float4*)(W + (size_t)(kk + k)*N + bn + n4*4);
      uint4 u;
      u.x = f2tf32(v.x); u.y = f2tf32(v.y); u.z = f2tf32(v.z); u.w = f2tf32(v.w);
      *(uint4*)(sB + k*132 + n4*4) = u;
    }
    __syncthreads();
    #pragma unroll
    for (int ks = 0; ks < 4; ks++){
      int k0 = ks*8;
      uint32_t a[2][4];
      #pragma unroll
      for (int mf = 0; mf < 2; mf++){
        int row = wm*32 + mf*16 + gid;
        a[mf][0] = sA[(k0 + tidg    )*SA_STRIDE + row];
        a[mf][1] = sA[(k0 + tidg    )*SA_STRIDE + row + 8];
        a[mf][2] = sA[(k0 + tidg + 4)*SA_STRIDE + row];
        a[mf][3] = sA[(k0 + tidg + 4)*SA_STRIDE + row + 8];
      }
      #pragma unroll
      for (int nf = 0; nf < 8; nf++){
        int col = wn*64 + nf*8 + gid;
        uint32_t b0 = sB[(k0 + tidg    )*132 + col];
        uint32_t b1 = sB[(k0 + tidg + 4)*132 + col];
        mma_tf32(acc[nf],     a[0], b0, b1);
        mma_tf32(acc[8 + nf], a[1], b0, b1);
      }
    }
    __syncthreads();
  }
  // epilogue: fused bias + activation
  #pragma unroll
  for (int mf = 0; mf < 2; mf++){
    #pragma unroll
    for (int nf = 0; nf < 8; nf++){
      float* cc = acc[mf*8 + nf];
      int row = bm + wm*32 + mf*16 + gid;
      int col = bn + wn*64 + nf*8 + tidg*2;
      float b0v = bias[col], b1v = bias[col+1];
      float2 v0, v1;
      v0.x = act_apply(cc[0] + b0v, act);
      v0.y = act_apply(cc[1] + b1v, act);
      v1.x = act_apply(cc[2] + b0v, act);
      v1.y = act_apply(cc[3] + b1v, act);
      *(float2*)(C + (size_t)row*N + col)     = v0;
      *(float2*)(C + (size_t)(row+8)*N + col) = v1;
    }
  }
}

// ---------------- persistent bi-LSTM (time loop inside; grid barrier per step) ----
__global__ __launch_bounds__(256) void lstm_kernel(
    const float* __restrict__ xgf, const float* __restrict__ xgb,
    const float* __restrict__ Whh_f, const float* __restrict__ Whh_b,
    const float* __restrict__ bhh_f, const float* __restrict__ bhh_b,
    float* __restrict__ hbi)
{
  __shared__ float sA[32][32];
  __shared__ float sB[4][32][33];
  int tid = threadIdx.x, blk = blockIdx.x;
  int dir = blk >> 6;
  int bt  = (blk >> 3) & 7;
  int jt  = blk & 7;
  int b0 = bt*32, j0 = jt*32;
  const float* xg  = dir ? xgb   : xgf;
  const float* Whh = dir ? Whh_b : Whh_f;
  const float* bhh = dir ? bhh_b : bhh_f;
  int tx = tid & 31, ty = tid >> 5;

  float bh[4];
  #pragma unroll
  for (int g = 0; g < 4; g++) bh[g] = bhh[g*Hz + j0 + tx];

  float c_reg[4] = {0.f,0.f,0.f,0.f};
  unsigned target = 0;

  for (int t = 0; t < TAz; t++){
    int te = dir ? (TAz-1-t) : t;
    float acc[4][4] = {{0,0,0,0},{0,0,0,0},{0,0,0,0},{0,0,0,0}};
    if (t > 0){
      int tp = dir ? te+1 : te-1;
      for (int kk = 0; kk < Hz; kk += 32){
        #pragma unroll
        for (int i = 0; i < 4; i++){
          int idx = tid + i*256;
          int r = idx >> 5, c = idx & 31;
          sA[r][c] = __ldcg(&hbi[((size_t)(b0+r)*TAz + tp)*512 + dir*Hz + kk + c]);
        }
        #pragma unroll
        for (int i = 0; i < 16; i++){
          int idx = tid + i*256;
          int g = idx >> 10, rem = idx & 1023;
          int k = rem >> 5, j = rem & 31;
          sB[g][k][j] = Whh[(kk + k)*(4*Hz) + g*Hz + j0 + j];
        }
        __syncthreads();
        #pragma unroll
        for (int k = 0; k < 32; k++){
          float bg0 = sB[0][k][tx], bg1 = sB[1][k][tx];
          float bg2 = sB[2][k][tx], bg3 = sB[3][k][tx];
          #pragma unroll
          for (int rr = 0; rr < 4; rr++){
            float a = sA[ty*4+rr][k];
            acc[0][rr] += a*bg0; acc[1][rr] += a*bg1;
            acc[2][rr] += a*bg2; acc[3][rr] += a*bg3;
          }
        }
        __syncthreads();
      }
    }
    #pragma unroll
    for (int rr = 0; rr < 4; rr++){
      int b = b0 + ty*4 + rr;
      size_t base = ((size_t)b*TAz + te)*(4*Hz) + j0 + tx;
      float gi = acc[0][rr] + xg[base + 0*Hz] + bh[0];
      float gf = acc[1][rr] + xg[base + 1*Hz] + bh[1];
      float gg = acc[2][rr] + xg[base + 2*Hz] + bh[2];
      float go = acc[3][rr] + xg[base + 3*Hz] + bh[3];
      float c = sigf(gf)*c_reg[rr] + sigf(gi)*tanhf(gg);
      c_reg[rr] = c;
      hbi[((size_t)b*TAz + te)*512 + dir*Hz + j0 + tx] = sigf(go)*tanhf(c);
    }
    target += 128u;
    gridsync(target);
  }
}

// ---------------- persistent GRU ----------------
__global__ __launch_bounds__(256) void gru_kernel(
    const float* __restrict__ xgg, const float* __restrict__ Whh,
    const float* __restrict__ bhh, float* __restrict__ h_out)
{
  __shared__ float sA[32][32];
  __shared__ float sB[3][32][33];
  int tid = threadIdx.x, blk = blockIdx.x;
  int bt = blk >> 4, jt = blk & 15;
  int b0 = bt*32, j0 = jt*32;
  int tx = tid & 31, ty = tid >> 5;

  float bh[3];
  #pragma unroll
  for (int g = 0; g < 3; g++) bh[g] = bhh[g*Dz + j0 + tx];

  unsigned target = 0;
  for (int t = 0; t < THz; t++){
    float acc[3][4] = {{0,0,0,0},{0,0,0,0},{0,0,0,0}};
    if (t > 0){
      for (int kk = 0; kk < Dz; kk += 32){
        #pragma unroll
        for (int i = 0; i < 4; i++){
          int idx = tid + i*256;
          int r = idx >> 5, c = idx & 31;
          sA[r][c] = __ldcg(&h_out[((size_t)(b0+r)*THz + (t-1))*Dz + kk + c]);
        }
        #pragma unroll
        for (int i = 0; i < 12; i++){
          int idx = tid + i*256;
          int g = idx >> 10, rem = idx & 1023;
          int k = rem >> 5, j = rem & 31;
          sB[g][k][j] = Whh[(kk + k)*(3*Dz) + g*Dz + j0 + j];
        }
        __syncthreads();
        #pragma unroll
        for (int k = 0; k < 32; k++){
          float bg0 = sB[0][k][tx], bg1 = sB[1][k][tx], bg2 = sB[2][k][tx];
          #pragma unroll
          for (int rr = 0; rr < 4; rr++){
            float a = sA[ty*4+rr][k];
            acc[0][rr] += a*bg0; acc[1][rr] += a*bg1; acc[2][rr] += a*bg2;
          }
        }
        __syncthreads();
      }
    }
    #pragma unroll
    for (int rr = 0; rr < 4; rr++){
      int b = b0 + ty*4 + rr;
      size_t xbase = ((size_t)b*THz + t)*(3*Dz) + j0 + tx;
      float xr = xgg[xbase + 0*Dz], xz = xgg[xbase + 1*Dz], xn = xgg[xbase + 2*Dz];
      float r = sigf(xr + acc[0][rr] + bh[0]);
      float z = sigf(xz + acc[1][rr] + bh[1]);
      float n = tanhf(xn + r*(acc[2][rr] + bh[2]));
      float hp = (t > 0) ? __ldcg(&h_out[((size_t)b*THz + (t-1))*Dz + j0 + tx]) : 0.f;
      h_out[((size_t)b*THz + t)*Dz + j0 + tx] = (1.f - z)*n + z*hp;
    }
    target += 128u;
    gridsync(target);
  }
}

// ---------------- fold W_e2 @ W_head into one vector + scalar ----------------
__global__ void w2h_kernel(const float* __restrict__ W_e2, const float* __restrict__ b_e2,
                           const float* __restrict__ W_head, const float* __restrict__ b_head)
{
  int tid = threadIdx.x;
  for (int d = tid; d < Dz; d += 256){
    float s = 0.f;
    for (int j = 0; j < Dz; j++) s += W_e2[(size_t)d*Dz + j]*W_head[j];
    g_w2h[d] = s;
  }
  if (tid == 0){
    float s = 0.f;
    for (int j = 0; j < Dz; j++) s += b_e2[j]*W_head[j];
    g_w2h[Dz] = s + b_head[0];
  }
}

// ---------------- build cat = [h_seq, qm + qs*eps] ----------------
__global__ __launch_bounds__(256) void cat_kernel(
    const float* __restrict__ h, const float* __restrict__ qm,
    const float* __restrict__ qs, const float* __restrict__ eps,
    float* __restrict__ cat)
{
  int row = blockIdx.x;               // b*TH + t
  int tid = threadIdx.x;
  float* dst = cat + (size_t)row*(Dz+Lz);
  const float* hs = h + (size_t)row*Dz;
  for (int i = tid; i < Dz; i += 256) dst[i] = hs[i];
  int b = row >> 9, t = row & 511;
  size_t q = ((size_t)b*TAz + t)*Lz;
  size_t e = (size_t)row*Lz;
  for (int i = tid; i < Lz; i += 256) dst[Dz+i] = qm[q+i] + qs[q+i]*eps[e+i];
}

// ---------------- y = gelu_out @ w2h + c2 ----------------
__global__ __launch_bounds__(256) void y_kernel(const float* __restrict__ gel,
                                                float* __restrict__ out_y)
{
  __shared__ float sw[Dz];
  __shared__ float c2s;
  int tid = threadIdx.x;
  for (int i = tid; i < Dz; i += 256) sw[i] = g_w2h[i];
  if (tid == 0) c2s = g_w2h[Dz];
  __syncthreads();
  int lane = tid & 31;
  int warp = (blockIdx.x*blockDim.x + tid) >> 5;
  int nwarp = (gridDim.x*blockDim.x) >> 5;
  for (int row = warp; row < Bz*THz; row += nwarp){
    const float* g = gel + (size_t)row*Dz;
    float s = 0.f;
    #pragma unroll
    for (int i = 0; i < Dz/32; i++) s += g[lane + i*32]*sw[lane + i*32];
    #pragma unroll
    for (int o = 16; o; o >>= 1) s += __shfl_xor_sync(0xffffffffu, s, o);
    if (lane == 0) out_y[row] = s + c2s;
  }
}

// ---------------- launch ----------------
extern "C" void kernel_launch(void* const* d_in, const int* in_sizes, int n_in,
                              void* d_out, int out_size)
{
  (void)in_sizes; (void)n_in; (void)out_size;
  const float* patches_hist = (const float*)d_in[0];
  const float* patches_all  = (const float*)d_in[1];
  const float* eps    = (const float*)d_in[2];
  const float* W_embed= (const float*)d_in[3];
  const float* b_embed= (const float*)d_in[4];
  const float* Wih_f  = (const float*)d_in[5];
  const float* Whh_f  = (const float*)d_in[6];
  const float* bih_f  = (const float*)d_in[7];
  const float* bhh_f  = (const float*)d_in[8];
  const float* Wih_b  = (const float*)d_in[9];
  const float* Whh_b  = (const float*)d_in[10];
  const float* bih_b  = (const float*)d_in[11];
  const float* bhh_b  = (const float*)d_in[12];
  const float* Wqm    = (const float*)d_in[13];
  const float* bqm    = (const float*)d_in[14];
  const float* Wqs    = (const float*)d_in[15];
  const float* bqs    = (const float*)d_in[16];
  const float* Wih_g  = (const float*)d_in[17];
  const float* Whh_g  = (const float*)d_in[18];
  const float* bih_g  = (const float*)d_in[19];
  const float* bhh_g  = (const float*)d_in[20];
  const float* Wpm    = (const float*)d_in[21];
  const float* bpm    = (const float*)d_in[22];
  const float* Wps    = (const float*)d_in[23];
  const float* bps    = (const float*)d_in[24];
  const float* W_e1   = (const float*)d_in[25];
  const float* b_e1   = (const float*)d_in[26];
  const float* W_e2   = (const float*)d_in[27];
  const float* b_e2   = (const float*)d_in[28];
  const float* W_head = (const float*)d_in[29];
  const float* b_head = (const float*)d_in[30];
  float* out = (float*)d_out;

  // output layout: y_hist, prior_m, prior_s, qm_all, qs_all, h_seq (flattened, concatenated)
  float* out_y  = out + 0;
  float* out_pm = out + 131072;
  float* out_ps = out + 16908288;
  float* out_qm = out + 33685504;
  float* out_qs = out + 52559872;
  float* out_h  = out + 71434240;

  float *x_hist, *x_all, *xgf, *xgb, *xgg, *hbi;
  cudaGetSymbolAddress((void**)&x_hist, g_x_hist);
  cudaGetSymbolAddress((void**)&x_all,  g_x_all);
  cudaGetSymbolAddress((void**)&xgf,    g_xgf);
  cudaGetSymbolAddress((void**)&xgb,    g_xgb);
  cudaGetSymbolAddress((void**)&xgg,    g_xgg);
  cudaGetSymbolAddress((void**)&hbi,    g_hbi);
  float* cat = xgf;     // reuse: xgf dead after LSTM steps
  float* gel = x_all;   // reuse: x_all dead after xg GEMMs

  // 1. embed
  embed_kernel<<<(Bz*TAz)/64, 256>>>(patches_all,  W_embed, b_embed, x_all);
  embed_kernel<<<(Bz*THz)/64, 256>>>(patches_hist, W_embed, b_embed, x_hist);

  // 2. input-gate GEMMs (tf32 mma.sync)
  tgemm_kernel<<<dim3(1024/128, (Bz*TAz)/128), 256>>>(x_all,  Wih_f, bih_f, xgf, Bz*TAz, 1024, 512, 0);
  tgemm_kernel<<<dim3(1024/128, (Bz*TAz)/128), 256>>>(x_all,  Wih_b, bih_b, xgb, Bz*TAz, 1024, 512, 0);
  tgemm_kernel<<<dim3(1536/128, (Bz*THz)/128), 256>>>(x_hist, Wih_g, bih_g, xgg, Bz*THz, 1536, 512, 0);

  // 3. recurrences: persistent kernels, software grid barrier
  reset_bar_kernel<<<1,1>>>();
  lstm_kernel<<<128,256>>>(xgf, xgb, Whh_f, Whh_b, bhh_f, bhh_b, hbi);
  reset_bar_kernel<<<1,1>>>();
  gru_kernel<<<128,256>>>(xgg, Whh_g, bhh_g, out_h);

  // 4. posterior / prior heads (tf32 mma.sync)
  tgemm_kernel<<<dim3(1, (Bz*TAz)/128), 256>>>(hbi,   Wqm, bqm, out_qm, Bz*TAz, 128, 512, 0);
  tgemm_kernel<<<dim3(1, (Bz*TAz)/128), 256>>>(hbi,   Wqs, bqs, out_qs, Bz*TAz, 128, 512, 1);
  tgemm_kernel<<<dim3(1, (Bz*THz)/128), 256>>>(out_h, Wpm, bpm, out_pm, Bz*THz, 128, 512, 0);
  tgemm_kernel<<<dim3(1, (Bz*THz)/128), 256>>>(out_h, Wps, bps, out_ps, Bz*THz, 128, 512, 1);

  // 5. emission (head folded: y = gelu(cat@W_e1+b_e1) @ (W_e2@W_head) + (b_e2@W_head + b_head))
  w2h_kernel<<<1,256>>>(W_e2, b_e2, W_head, b_head);
  cat_kernel<<<Bz*THz, 256>>>(out_h, out_qm, out_qs, eps, cat);
  tgemm_kernel<<<dim3(512/128, (Bz*THz)/128), 256>>>(cat, W_e1, b_e1, gel, Bz*THz, 512, 640, 2);
  y_kernel<<<2048,256>>>(gel, out_y);
}

// round 14
// speedup vs baseline: 1.5943x; 1.2104x over previous
#include <cuda_runtime.h>
#include <cstdint>

#define Bz  256
#define THz 512
#define TAz 576
#define Pz  16
#define Dz  512
#define Lz  128
#define Hz  256

// ---------------- scratch (static device globals; no allocation) ----------------
__device__ float g_x_hist[Bz*THz*Dz];          // [B,TH,D]
__device__ float g_x_all [Bz*TAz*Dz];          // [B,TA,D]; reused later as gelu output [B,TH,D]
__device__ float g_xgf   [Bz*TAz*4*Hz];        // [B,TA,4H]; reused later as cat [B,TH,D+L]
__device__ float g_xgb   [Bz*TAz*4*Hz];
__device__ float g_xgg   [Bz*THz*3*Dz];        // [B,TH,3D]
__device__ float g_hbi   [Bz*TAz*Dz];          // [B,TA,2H] (hf | hb)
__device__ float g_w2h   [Dz+1];               // W_e2@W_head, plus scalar c2 at [Dz]
__device__ unsigned g_bar;

// ---------------- helpers ----------------
__device__ __forceinline__ float sigf(float x){ return 1.f/(1.f+expf(-x)); }

__device__ __forceinline__ float act_apply(float v, int act){
  if (act == 1){                      // softplus + 1e-5 (stable logaddexp(x,0))
    v = fmaxf(v, 0.f) + log1pf(expf(-fabsf(v))) + 1e-5f;
  } else if (act == 2){               // exact GELU
    v = 0.5f*v*(1.f + erff(v*0.7071067811865476f));
  }
  return v;
}

__device__ __forceinline__ uint32_t f2tf32(float f){
  uint32_t u; asm("cvt.rna.tf32.f32 %0, %1;" : "=r"(u) : "f"(f)); return u;
}
__device__ __forceinline__ void tf32split(float x, uint32_t& hi, uint32_t& lo){
  hi = f2tf32(x);
  lo = f2tf32(x - __uint_as_float(hi));
}

// m16n8k8 tf32 MMA (legacy tensor path; plain-PTX, works on sm_103 target)
__device__ __forceinline__ void mma_tf32(float* c, const uint32_t* a, uint32_t b0, uint32_t b1){
  asm volatile("mma.sync.aligned.m16n8k8.row.col.f32.tf32.tf32.f32 "
      "{%0,%1,%2,%3}, {%4,%5,%6,%7}, {%8,%9}, {%0,%1,%2,%3};"
      : "+f"(c[0]), "+f"(c[1]), "+f"(c[2]), "+f"(c[3])
      : "r"(a[0]), "r"(a[1]), "r"(a[2]), "r"(a[3]), "r"(b0), "r"(b1));
}

__device__ __forceinline__ void gridsync(unsigned target){
  __threadfence();
  __syncthreads();
  if (threadIdx.x == 0){
    atomicAdd(&g_bar, 1u);
    long long start = clock64();
    unsigned v;
    do {
      asm volatile("ld.global.cg.u32 %0, [%1];" : "=r"(v) : "l"(&g_bar));
      if (v >= target) break;
      __nanosleep(64);
    } while (clock64() - start < 40000000000LL);
    __threadfence();
  }
  __syncthreads();
}

__global__ void reset_bar_kernel(){ g_bar = 0u; }

// ---------------- embed: X = patches @ W_embed + b ----------------
__global__ __launch_bounds__(256) void embed_kernel(
    const float* __restrict__ patches, const float* __restrict__ W,
    const float* __restrict__ bias, float* __restrict__ X)
{
  __shared__ float sW[Pz*Dz];
  __shared__ float sb[Dz];
  __shared__ float sP[64*Pz];
  int tid = threadIdx.x;
  for (int i = tid; i < Pz*Dz; i += 256) sW[i] = W[i];
  for (int i = tid; i < Dz;    i += 256) sb[i] = bias[i];
  size_t r0 = (size_t)blockIdx.x * 64;
  for (int i = tid; i < 64*Pz; i += 256) sP[i] = patches[r0*Pz + i];
  __syncthreads();
  for (int rr = 0; rr < 64; rr++){
    const float* pv = sP + rr*Pz;
    #pragma unroll
    for (int half = 0; half < 2; half++){
      int d = tid + half*256;
      float acc = sb[d];
      #pragma unroll
      for (int p = 0; p < Pz; p++) acc += pv[p]*sW[p*Dz + d];
      X[(r0+rr)*Dz + d] = acc;
    }
  }
}

// ---------------- tf32 mma.sync GEMM: C[M,N] = A[M,K] @ W[K,N] + bias, act ----------
#define SA_STRIDE 133
__global__ __launch_bounds__(256) void tgemm_kernel(
    const float* __restrict__ A, const float* __restrict__ W,
    const float* __restrict__ bias, float* __restrict__ C,
    int M, int N, int K, int act)
{
  __shared__ uint32_t sA[32*SA_STRIDE];  // [k][m]
  __shared__ uint32_t sB[32*132];        // [k][n]
  int tid = threadIdx.x;
  int lane = tid & 31, warp = tid >> 5;
  int wm = warp & 3, wn = warp >> 2;
  int gid = lane >> 2, tidg = lane & 3;
  int bm = blockIdx.y*128, bn = blockIdx.x*128;

  float acc[16][4];
  #pragma unroll
  for (int i = 0; i < 16; i++)
    #pragma unroll
    for (int j = 0; j < 4; j++) acc[i][j] = 0.f;

  for (int kk = 0; kk < K; kk += 32){
    #pragma unroll
    for (int i = 0; i < 4; i++){
      int linear = tid + i*256;
      int r  = linear >> 3;
      int c4 = linear & 7;
      float4 v = *(const float4*)(A + (size_t)(bm + r)*K + kk + c4*4);
      sA[(c4*4+0)*SA_STRIDE + r] = f2tf32(v.x);
      sA[(c4*4+1)*SA_STRIDE + r] = f2tf32(v.y);
      sA[(c4*4+2)*SA_STRIDE + r] = f2tf32(v.z);
      sA[(c4*4+3)*SA_STRIDE + r] = f2tf32(v.w);
    }
    #pragma unroll
    for (int i = 0; i < 4; i++){
      int linear = tid + i*256;
      int k  = linear >> 5;
      int n4 = linear & 31;
      float4 v = *(const float4*)(W + (size_t)(kk + k)*N + bn + n4*4);
      uint4 u;
      u.x = f2tf32(v.x); u.y = f2tf32(v.y); u.z = f2tf32(v.z); u.w = f2tf32(v.w);
      *(uint4*)(sB + k*132 + n4*4) = u;
    }
    __syncthreads();
    #pragma unroll
    for (int ks = 0; ks < 4; ks++){
      int k0 = ks*8;
      uint32_t a[2][4];
      #pragma unroll
      for (int mf = 0; mf < 2; mf++){
        int row = wm*32 + mf*16 + gid;
        a[mf][0] = sA[(k0 + tidg    )*SA_STRIDE + row];
        a[mf][1] = sA[(k0 + tidg    )*SA_STRIDE + row + 8];
        a[mf][2] = sA[(k0 + tidg + 4)*SA_STRIDE + row];
        a[mf][3] = sA[(k0 + tidg + 4)*SA_STRIDE + row + 8];
      }
      #pragma unroll
      for (int nf = 0; nf < 8; nf++){
        int col = wn*64 + nf*8 + gid;
        uint32_t b0 = sB[(k0 + tidg    )*132 + col];
        uint32_t b1 = sB[(k0 + tidg + 4)*132 + col];
        mma_tf32(acc[nf],     a[0], b0, b1);
        mma_tf32(acc[8 + nf], a[1], b0, b1);
      }
    }
    __syncthreads();
  }
  #pragma unroll
  for (int mf = 0; mf < 2; mf++){
    #pragma unroll
    for (int nf = 0; nf < 8; nf++){
      float* cc = acc[mf*8 + nf];
      int row = bm + wm*32 + mf*16 + gid;
      int col = bn + wn*64 + nf*8 + tidg*2;
      float b0v = bias[col], b1v = bias[col+1];
      float2 v0, v1;
      v0.x = act_apply(cc[0] + b0v, act);
      v0.y = act_apply(cc[1] + b1v, act);
      v1.x = act_apply(cc[2] + b0v, act);
      v1.y = act_apply(cc[3] + b1v, act);
      *(float2*)(C + (size_t)row*N + col)     = v0;
      *(float2*)(C + (size_t)(row+8)*N + col) = v1;
    }
  }
}

// ---------------- persistent bi-LSTM with tf32x2 tensor-core steps ----------------
// 128 blocks (1/SM): dir(2) x bt(8) x jt(8). Block: 32 batch x (4 gates x 32 hid).
// Whh slice resident in dynamic smem for the whole kernel.
#define LSW 136   // sW stride [256][136]
#define LSH 260   // sH stride [32][260]; aliased as sG [32][132]
extern __shared__ float dynsmem[];

__global__ __launch_bounds__(256, 1) void lstm_kernel(
    const float* __restrict__ xgf, const float* __restrict__ xgb,
    const float* __restrict__ Whh_f, const float* __restrict__ Whh_b,
    const float* __restrict__ bhh_f, const float* __restrict__ bhh_b,
    float* __restrict__ hbi)
{
  float* sW = dynsmem;                 // [256][LSW]
  float* sH = dynsmem + 256*LSW;       // [32][LSH]
  float* sG = sH;                      // alias: [32][132] gate exchange

  int tid = threadIdx.x, blk = blockIdx.x;
  int dir = blk >> 6;
  int bt  = (blk >> 3) & 7;
  int jt  = blk & 7;
  int b0 = bt*32, j0 = jt*32;
  const float* xg  = dir ? xgb   : xgf;
  const float* Whh = dir ? Whh_b : Whh_f;
  const float* bhh = dir ? bhh_b : bhh_f;
  int lane = tid & 31, warp = tid >> 5;
  int gid = lane >> 2, tidg = lane & 3;
  int gW = warp >> 1, nh = warp & 1;
  int colbase = gW*32 + nh*16;
  int ty = tid >> 5, tx = tid & 31;

  // preload Whh slice: sW[k][g*32+j] = Whh[k][g*256 + j0 + j]
  for (int idx = tid; idx < 256*128; idx += 256){
    int k = idx >> 7, c = idx & 127, g = c >> 5, j = c & 31;
    sW[k*LSW + c] = Whh[(size_t)k*(4*Hz) + g*Hz + j0 + j];
  }
  float bh[4];
  #pragma unroll
  for (int g = 0; g < 4; g++) bh[g] = bhh[g*Hz + j0 + tx];
  __syncthreads();

  float c_reg[4] = {0.f,0.f,0.f,0.f};
  unsigned target = 0;

  for (int t = 0; t < TAz; t++){
    int te = dir ? (TAz-1-t) : t;
    float acc[2][2][4];
    #pragma unroll
    for (int mi = 0; mi < 2; mi++)
      #pragma unroll
      for (int ni = 0; ni < 2; ni++)
        #pragma unroll
        for (int q = 0; q < 4; q++) acc[mi][ni][q] = 0.f;

    if (t > 0){
      int tp = dir ? te+1 : te-1;
      // stage h_prev 32x256 (this dir's half of hbi)
      #pragma unroll
      for (int i = 0; i < 8; i++){
        int idx = tid + i*256;
        int r = idx >> 6, c4 = idx & 63;
        float4 v = __ldcg((const float4*)&hbi[((size_t)(b0+r)*TAz + tp)*512 + dir*Hz + c4*4]);
        *(float4*)&sH[r*LSH + c4*4] = v;
      }
      __syncthreads();
      #pragma unroll 2
      for (int ks = 0; ks < 32; ks++){
        int k0 = ks*8;
        uint32_t ahi[2][4], alo[2][4];
        #pragma unroll
        for (int mi = 0; mi < 2; mi++){
          int row = mi*16 + gid;
          tf32split(sH[row*LSH + k0 + tidg],         ahi[mi][0], alo[mi][0]);
          tf32split(sH[(row+8)*LSH + k0 + tidg],     ahi[mi][1], alo[mi][1]);
          tf32split(sH[row*LSH + k0 + tidg + 4],     ahi[mi][2], alo[mi][2]);
          tf32split(sH[(row+8)*LSH + k0 + tidg + 4], ahi[mi][3], alo[mi][3]);
        }
        uint32_t bhi[2][2], blo[2][2];
        #pragma unroll
        for (int ni = 0; ni < 2; ni++){
          int col = colbase + ni*8 + gid;
          tf32split(sW[(k0 + tidg)*LSW + col],     bhi[ni][0], blo[ni][0]);
          tf32split(sW[(k0 + tidg + 4)*LSW + col], bhi[ni][1], blo[ni][1]);
        }
        #pragma unroll
        for (int mi = 0; mi < 2; mi++)
          #pragma unroll
          for (int ni = 0; ni < 2; ni++){
            mma_tf32(acc[mi][ni], alo[mi], bhi[ni][0], bhi[ni][1]);
            mma_tf32(acc[mi][ni], ahi[mi], blo[ni][0], blo[ni][1]);
            mma_tf32(acc[mi][ni], ahi[mi], bhi[ni][0], bhi[ni][1]);
          }
      }
      __syncthreads();   // all warps done reading sH before sG overwrite
    }
    // gate pre-activations -> sG [32][132]
    #pragma unroll
    for (int mi = 0; mi < 2; mi++)
      #pragma unroll
      for (int ni = 0; ni < 2; ni++){
        int r = mi*16 + gid;
        int c = colbase + ni*8 + tidg*2;
        sG[r*132 + c]       = acc[mi][ni][0];
        sG[r*132 + c + 1]   = acc[mi][ni][1];
        sG[(r+8)*132 + c]     = acc[mi][ni][2];
        sG[(r+8)*132 + c + 1] = acc[mi][ni][3];
      }
    __syncthreads();
    // nonlinear update: thread (ty,tx) owns rows ty*4..+3, col tx
    #pragma unroll
    for (int rr = 0; rr < 4; rr++){
      int rloc = ty*4 + rr;
      int b = b0 + rloc;
      size_t base = ((size_t)b*TAz + te)*(4*Hz) + j0 + tx;
      float gi = sG[rloc*132 +  0 + tx] + xg[base + 0*Hz] + bh[0];
      float gf = sG[rloc*132 + 32 + tx] + xg[base + 1*Hz] + bh[1];
      float gg = sG[rloc*132 + 64 + tx] + xg[base + 2*Hz] + bh[2];
      float go = sG[rloc*132 + 96 + tx] + xg[base + 3*Hz] + bh[3];
      float c = sigf(gf)*c_reg[rr] + sigf(gi)*tanhf(gg);
      c_reg[rr] = c;
      hbi[((size_t)b*TAz + te)*512 + dir*Hz + j0 + tx] = sigf(go)*tanhf(c);
    }
    target += 128u;
    gridsync(target);   // also orders sG reads before next step's sH writes
  }
}

// ---------------- persistent GRU with tf32x2 tensor-core steps ----------------
// 128 blocks (1/SM): bt(8) x jt(16). Block: 32 batch x (3 gates x 32 hid), K=512.
#define GSW 104   // sW stride [512][104]
#define GSH 132   // sH/sG stride [32][132]
__global__ __launch_bounds__(256, 1) void gru_kernel(
    const float* __restrict__ xgg, const float* __restrict__ Whh,
    const float* __restrict__ bhh, float* __restrict__ h_out)
{
  float* sW = dynsmem;             // [512][GSW]
  float* sH = dynsmem + 512*GSW;   // [32][GSH] chunk stage; alias gate exchange
  float* sG = sH;

  int tid = threadIdx.x, blk = blockIdx.x;
  int bt = blk >> 4, jt = blk & 15;
  int b0 = bt*32, j0 = jt*32;
  int lane = tid & 31, warp = tid >> 5;
  int gid = lane >> 2, tidg = lane & 3;
  int gW = warp >> 1, nh = warp & 1;       // valid for warp<6
  int colbase = gW*32 + nh*16;
  int ty = tid >> 5, tx = tid & 31;

  // preload Whh slice: sW[k][g*32+j] = Whh[k][g*512 + j0 + j]
  for (int idx = tid; idx < 512*96; idx += 256){
    int k = idx / 96, c = idx - k*96;
    int g = c >> 5, j = c & 31;
    sW[k*GSW + c] = Whh[(size_t)k*(3*Dz) + g*Dz + j0 + j];
  }
  float bh[3];
  #pragma unroll
  for (int g = 0; g < 3; g++) bh[g] = bhh[g*Dz + j0 + tx];
  __syncthreads();

  unsigned target = 0;
  for (int t = 0; t < THz; t++){
    float acc[2][2][4];
    #pragma unroll
    for (int mi = 0; mi < 2; mi++)
      #pragma unroll
      for (int ni = 0; ni < 2; ni++)
        #pragma unroll
        for (int q = 0; q < 4; q++) acc[mi][ni][q] = 0.f;

    if (t > 0){
      for (int cc = 0; cc < 4; cc++){
        // stage h_prev chunk 32x128
        #pragma unroll
        for (int i = 0; i < 4; i++){
          int idx = tid + i*256;
          int r = idx >> 5, c4 = idx & 31;
          float4 v = __ldcg((const float4*)&h_out[((size_t)(b0+r)*THz + (t-1))*Dz + cc*128 + c4*4]);
          *(float4*)&sH[r*GSH + c4*4] = v;
        }
        __syncthreads();
        if (warp < 6){
          #pragma unroll 2
          for (int ks = 0; ks < 16; ks++){
            int k0 = ks*8;
            uint32_t ahi[2][4], alo[2][4];
            #pragma unroll
            for (int mi = 0; mi < 2; mi++){
              int row = mi*16 + gid;
              tf32split(sH[row*GSH + k0 + tidg],         ahi[mi][0], alo[mi][0]);
              tf32split(sH[(row+8)*GSH + k0 + tidg],     ahi[mi][1], alo[mi][1]);
              tf32split(sH[row*GSH + k0 + tidg + 4],     ahi[mi][2], alo[mi][2]);
              tf32split(sH[(row+8)*GSH + k0 + tidg + 4], ahi[mi][3], alo[mi][3]);
            }
            uint32_t bhi[2][2], blo[2][2];
            #pragma unroll
            for (int ni = 0; ni < 2; ni++){
              int col = colbase + ni*8 + gid;
              int krow = cc*128 + k0 + tidg;
              tf32split(sW[krow*GSW + col],       bhi[ni][0], blo[ni][0]);
              tf32split(sW[(krow + 4)*GSW + col], bhi[ni][1], blo[ni][1]);
            }
            #pragma unroll
            for (int mi = 0; mi < 2; mi++)
              #pragma unroll
              for (int ni = 0; ni < 2; ni++){
                mma_tf32(acc[mi][ni], alo[mi], bhi[ni][0], bhi[ni][1]);
                mma_tf32(acc[mi][ni], ahi[mi], blo[ni][0], blo[ni][1]);
                mma_tf32(acc[mi][ni], ahi[mi], bhi[ni][0], bhi[ni][1]);
              }
          }
        }
        __syncthreads();
      }
    }
    // gate pre-activations -> sG (cols: g*32 + j, g in {r,z,n})
    if (warp < 6){
      #pragma unroll
      for (int mi = 0; mi < 2; mi++)
        #pragma unroll
        for (int ni = 0; ni < 2; ni++){
          int r = mi*16 + gid;
          int c = colbase + ni*8 + tidg*2;
          sG[r*GSH + c]       = acc[mi][ni][0];
          sG[r*GSH + c + 1]   = acc[mi][ni][1];
          sG[(r+8)*GSH + c]     = acc[mi][ni][2];
          sG[(r+8)*GSH + c + 1] = acc[mi][ni][3];
        }
    }
    __syncthreads();
    #pragma unroll
    for (int rr = 0; rr < 4; rr++){
      int rloc = ty*4 + rr;
      int b = b0 + rloc;
      size_t xbase = ((size_t)b*THz + t)*(3*Dz) + j0 + tx;
      float xr = xgg[xbase + 0*Dz], xz = xgg[xbase + 1*Dz], xn = xgg[xbase + 2*Dz];
      float hr = sG[rloc*GSH +  0 + tx];
      float hz = sG[rloc*GSH + 32 + tx];
      float hn = sG[rloc*GSH + 64 + tx];
      float r = sigf(xr + hr + bh[0]);
      float z = sigf(xz + hz + bh[1]);
      float n = tanhf(xn + r*(hn + bh[2]));
      float hp = (t > 0) ? __ldcg(&h_out[((size_t)b*THz + (t-1))*Dz + j0 + tx]) : 0.f;
      h_out[((size_t)b*THz + t)*Dz + j0 + tx] = (1.f - z)*n + z*hp;
    }
    target += 128u;
    gridsync(target);
  }
}

// ---------------- fold W_e2 @ W_head into one vector + scalar ----------------
__global__ void w2h_kernel(const float* __restrict__ W_e2, const float* __restrict__ b_e2,
                           const float* __restrict__ W_head, const float* __restrict__ b_head)
{
  int tid = threadIdx.x;
  for (int d = tid; d < Dz; d += 256){
    float s = 0.f;
    for (int j = 0; j < Dz; j++) s += W_e2[(size_t)d*Dz + j]*W_head[j];
    g_w2h[d] = s;
  }
  if (tid == 0){
    float s = 0.f;
    for (int j = 0; j < Dz; j++) s += b_e2[j]*W_head[j];
    g_w2h[Dz] = s + b_head[0];
  }
}

// ---------------- build cat = [h_seq, qm + qs*eps] ----------------
__global__ __launch_bounds__(256) void cat_kernel(
    const float* __restrict__ h, const float* __restrict__ qm,
    const float* __restrict__ qs, const float* __restrict__ eps,
    float* __restrict__ cat)
{
  int row = blockIdx.x;               // b*TH + t
  int tid = threadIdx.x;
  float* dst = cat + (size_t)row*(Dz+Lz);
  const float* hs = h + (size_t)row*Dz;
  for (int i = tid; i < Dz; i += 256) dst[i] = hs[i];
  int b = row >> 9, t = row & 511;
  size_t q = ((size_t)b*TAz + t)*Lz;
  size_t e = (size_t)row*Lz;
  for (int i = tid; i < Lz; i += 256) dst[Dz+i] = qm[q+i] + qs[q+i]*eps[e+i];
}

// ---------------- y = gelu_out @ w2h + c2 ----------------
__global__ __launch_bounds__(256) void y_kernel(const float* __restrict__ gel,
                                                float* __restrict__ out_y)
{
  __shared__ float sw[Dz];
  __shared__ float c2s;
  int tid = threadIdx.x;
  for (int i = tid; i < Dz; i += 256) sw[i] = g_w2h[i];
  if (tid == 0) c2s = g_w2h[Dz];
  __syncthreads();
  int lane = tid & 31;
  int warp = (blockIdx.x*blockDim.x + tid) >> 5;
  int nwarp = (gridDim.x*blockDim.x) >> 5;
  for (int row = warp; row < Bz*THz; row += nwarp){
    const float* g = gel + (size_t)row*Dz;
    float s = 0.f;
    #pragma unroll
    for (int i = 0; i < Dz/32; i++) s += g[lane + i*32]*sw[lane + i*32];
    #pragma unroll
    for (int o = 16; o; o >>= 1) s += __shfl_xor_sync(0xffffffffu, s, o);
    if (lane == 0) out_y[row] = s + c2s;
  }
}

// ---------------- launch ----------------
extern "C" void kernel_launch(void* const* d_in, const int* in_sizes, int n_in,
                              void* d_out, int out_size)
{
  (void)in_sizes; (void)n_in; (void)out_size;
  const float* patches_hist = (const float*)d_in[0];
  const float* patches_all  = (const float*)d_in[1];
  const float* eps    = (const float*)d_in[2];
  const float* W_embed= (const float*)d_in[3];
  const float* b_embed= (const float*)d_in[4];
  const float* Wih_f  = (const float*)d_in[5];
  const float* Whh_f  = (const float*)d_in[6];
  const float* bih_f  = (const float*)d_in[7];
  const float* bhh_f  = (const float*)d_in[8];
  const float* Wih_b  = (const float*)d_in[9];
  const float* Whh_b  = (const float*)d_in[10];
  const float* bih_b  = (const float*)d_in[11];
  const float* bhh_b  = (const float*)d_in[12];
  const float* Wqm    = (const float*)d_in[13];
  const float* bqm    = (const float*)d_in[14];
  const float* Wqs    = (const float*)d_in[15];
  const float* bqs    = (const float*)d_in[16];
  const float* Wih_g  = (const float*)d_in[17];
  const float* Whh_g  = (const float*)d_in[18];
  const float* bih_g  = (const float*)d_in[19];
  const float* bhh_g  = (const float*)d_in[20];
  const float* Wpm    = (const float*)d_in[21];
  const float* bpm    = (const float*)d_in[22];
  const float* Wps    = (const float*)d_in[23];
  const float* bps    = (const float*)d_in[24];
  const float* W_e1   = (const float*)d_in[25];
  const float* b_e1   = (const float*)d_in[26];
  const float* W_e2   = (const float*)d_in[27];
  const float* b_e2   = (const float*)d_in[28];
  const float* W_head = (const float*)d_in[29];
  const float* b_head = (const float*)d_in[30];
  float* out = (float*)d_out;

  // output layout: y_hist, prior_m, prior_s, qm_all, qs_all, h_seq (flattened, concatenated)
  float* out_y  = out + 0;
  float* out_pm = out + 131072;
  float* out_ps = out + 16908288;
  float* out_qm = out + 33685504;
  float* out_qs = out + 52559872;
  float* out_h  = out + 71434240;

  float *x_hist, *x_all, *xgf, *xgb, *xgg, *hbi;
  cudaGetSymbolAddress((void**)&x_hist, g_x_hist);
  cudaGetSymbolAddress((void**)&x_all,  g_x_all);
  cudaGetSymbolAddress((void**)&xgf,    g_xgf);
  cudaGetSymbolAddress((void**)&xgb,    g_xgb);
  cudaGetSymbolAddress((void**)&xgg,    g_xgg);
  cudaGetSymbolAddress((void**)&hbi,    g_hbi);
  float* cat = xgf;     // reuse: xgf dead after LSTM steps
  float* gel = x_all;   // reuse: x_all dead after xg GEMMs

  const int LSTM_SMEM = (256*LSW + 32*LSH)*4;   // 172,544 B
  const int GRU_SMEM  = (512*GSW + 32*GSH)*4;   // 229,888 B
  static int attr_done = 0;
  if (!attr_done){
    cudaFuncSetAttribute(lstm_kernel, cudaFuncAttributeMaxDynamicSharedMemorySize, LSTM_SMEM);
    cudaFuncSetAttribute(gru_kernel,  cudaFuncAttributeMaxDynamicSharedMemorySize, GRU_SMEM);
    attr_done = 1;
  }

  // 1. embed
  embed_kernel<<<(Bz*TAz)/64, 256>>>(patches_all,  W_embed, b_embed, x_all);
  embed_kernel<<<(Bz*THz)/64, 256>>>(patches_hist, W_embed, b_embed, x_hist);

  // 2. input-gate GEMMs (tf32 mma.sync)
  tgemm_kernel<<<dim3(1024/128, (Bz*TAz)/128), 256>>>(x_all,  Wih_f, bih_f, xgf, Bz*TAz, 1024, 512, 0);
  tgemm_kernel<<<dim3(1024/128, (Bz*TAz)/128), 256>>>(x_all,  Wih_b, bih_b, xgb, Bz*TAz, 1024, 512, 0);
  tgemm_kernel<<<dim3(1536/128, (Bz*THz)/128), 256>>>(x_hist, Wih_g, bih_g, xgg, Bz*THz, 1536, 512, 0);

  // 3. recurrences: persistent tensor-core kernels, software grid barrier
  reset_bar_kernel<<<1,1>>>();
  lstm_kernel<<<128,256,LSTM_SMEM>>>(xgf, xgb, Whh_f, Whh_b, bhh_f, bhh_b, hbi);
  reset_bar_kernel<<<1,1>>>();
  gru_kernel<<<128,256,GRU_SMEM>>>(xgg, Whh_g, bhh_g, out_h);

  // 4. posterior / prior heads (tf32 mma.sync)
  tgemm_kernel<<<dim3(1, (Bz*TAz)/128), 256>>>(hbi,   Wqm, bqm, out_qm, Bz*TAz, 128, 512, 0);
  tgemm_kernel<<<dim3(1, (Bz*TAz)/128), 256>>>(hbi,   Wqs, bqs, out_qs, Bz*TAz, 128, 512, 1);
  tgemm_kernel<<<dim3(1, (Bz*THz)/128), 256>>>(out_h, Wpm, bpm, out_pm, Bz*THz, 128, 512, 0);
  tgemm_kernel<<<dim3(1, (Bz*THz)/128), 256>>>(out_h, Wps, bps, out_ps, Bz*THz, 128, 512, 1);

  // 5. emission (head folded: y = gelu(cat@W_e1+b_e1) @ (W_e2@W_head) + (b_e2@W_head + b_head))
  w2h_kernel<<<1,256>>>(W_e2, b_e2, W_head, b_head);
  cat_kernel<<<Bz*THz, 256>>>(out_h, out_qm, out_qs, eps, cat);
  tgemm_kernel<<<dim3(512/128, (Bz*THz)/128), 256>>>(cat, W_e1, b_e1, gel, Bz*THz, 512, 640, 2);
  y_kernel<<<2048,256>>>(gel, out_y);
}

// round 16
// speedup vs baseline: 2.3303x; 1.4616x over previous
#include <cuda_runtime.h>
#include <cstdint>

#define Bz  256
#define THz 512
#define TAz 576
#define Pz  16
#define Dz  512
#define Lz  128
#define Hz  256

// ---------------- scratch (static device globals; no allocation) ----------------
__device__ float g_x_hist[Bz*THz*Dz];          // [B,TH,D]
__device__ float g_x_all [Bz*TAz*Dz];          // [B,TA,D]; reused later as gelu output [B,TH,D]
__device__ float g_xgf   [Bz*TAz*4*Hz];        // [B,TA,4H]; reused later as cat [B,TH,D+L]
__device__ float g_xgb   [Bz*TAz*4*Hz];
__device__ float g_xgg   [Bz*THz*3*Dz];        // [B,TH,3D]
__device__ float g_hbi   [Bz*TAz*Dz];          // [B,TA,2H] (hf | hb)
__device__ float g_w2h   [Dz+1];               // W_e2@W_head, plus scalar c2 at [Dz]
__device__ unsigned g_bar;

// ---------------- helpers ----------------
__device__ __forceinline__ float sigf(float x){ return 1.f/(1.f+expf(-x)); }

__device__ __forceinline__ float act_apply(float v, int act){
  if (act == 1){                      // softplus + 1e-5 (stable logaddexp(x,0))
    v = fmaxf(v, 0.f) + log1pf(expf(-fabsf(v))) + 1e-5f;
  } else if (act == 2){               // exact GELU
    v = 0.5f*v*(1.f + erff(v*0.7071067811865476f));
  }
  return v;
}

__device__ __forceinline__ uint32_t f2tf32(float f){
  uint32_t u; asm("cvt.rna.tf32.f32 %0, %1;" : "=r"(u) : "f"(f)); return u;
}

// m16n8k8 tf32 MMA (legacy tensor path; plain-PTX, works on sm_103 target)
__device__ __forceinline__ void mma_tf32(float* c, const uint32_t* a, uint32_t b0, uint32_t b1){
  asm volatile("mma.sync.aligned.m16n8k8.row.col.f32.tf32.tf32.f32 "
      "{%0,%1,%2,%3}, {%4,%5,%6,%7}, {%8,%9}, {%0,%1,%2,%3};"
      : "+f"(c[0]), "+f"(c[1]), "+f"(c[2]), "+f"(c[3])
      : "r"(a[0]), "r"(a[1]), "r"(a[2]), "r"(a[3]), "r"(b0), "r"(b1));
}

__device__ __forceinline__ void gridsync(unsigned target){
  __threadfence();
  __syncthreads();
  if (threadIdx.x == 0){
    atomicAdd(&g_bar, 1u);
    long long start = clock64();
    unsigned v;
    do {
      asm volatile("ld.global.cg.u32 %0, [%1];" : "=r"(v) : "l"(&g_bar));
      if (v >= target) break;
      __nanosleep(32);
    } while (clock64() - start < 40000000000LL);
    __threadfence();
  }
  __syncthreads();
}

__global__ void reset_bar_kernel(){ g_bar = 0u; }

// ---------------- embed: X = patches @ W_embed + b ----------------
__global__ __launch_bounds__(256) void embed_kernel(
    const float* __restrict__ patches, const float* __restrict__ W,
    const float* __restrict__ bias, float* __restrict__ X)
{
  __shared__ float sW[Pz*Dz];
  __shared__ float sb[Dz];
  __shared__ float sP[64*Pz];
  int tid = threadIdx.x;
  for (int i = tid; i < Pz*Dz; i += 256) sW[i] = W[i];
  for (int i = tid; i < Dz;    i += 256) sb[i] = bias[i];
  size_t r0 = (size_t)blockIdx.x * 64;
  for (int i = tid; i < 64*Pz; i += 256) sP[i] = patches[r0*Pz + i];
  __syncthreads();
  for (int rr = 0; rr < 64; rr++){
    const float* pv = sP + rr*Pz;
    #pragma unroll
    for (int half = 0; half < 2; half++){
      int d = tid + half*256;
      float acc = sb[d];
      #pragma unroll
      for (int p = 0; p < Pz; p++) acc += pv[p]*sW[p*Dz + d];
      X[(r0+rr)*Dz + d] = acc;
    }
  }
}

// ---------------- tf32 mma.sync GEMM: C[M,N] = A[M,K] @ W[K,N] + bias, act ----------
#define SA_STRIDE 133
__global__ __launch_bounds__(256) void tgemm_kernel(
    const float* __restrict__ A, const float* __restrict__ W,
    const float* __restrict__ bias, float* __restrict__ C,
    int M, int N, int K, int act)
{
  __shared__ uint32_t sA[32*SA_STRIDE];  // [k][m]
  __shared__ uint32_t sB[32*132];        // [k][n]
  int tid = threadIdx.x;
  int lane = tid & 31, warp = tid >> 5;
  int wm = warp & 3, wn = warp >> 2;
  int gid = lane >> 2, tidg = lane & 3;
  int bm = blockIdx.y*128, bn = blockIdx.x*128;

  float acc[16][4];
  #pragma unroll
  for (int i = 0; i < 16; i++)
    #pragma unroll
    for (int j = 0; j < 4; j++) acc[i][j] = 0.f;

  for (int kk = 0; kk < K; kk += 32){
    #pragma unroll
    for (int i = 0; i < 4; i++){
      int linear = tid + i*256;
      int r  = linear >> 3;
      int c4 = linear & 7;
      float4 v = *(const float4*)(A + (size_t)(bm + r)*K + kk + c4*4);
      sA[(c4*4+0)*SA_STRIDE + r] = f2tf32(v.x);
      sA[(c4*4+1)*SA_STRIDE + r] = f2tf32(v.y);
      sA[(c4*4+2)*SA_STRIDE + r] = f2tf32(v.z);
      sA[(c4*4+3)*SA_STRIDE + r] = f2tf32(v.w);
    }
    #pragma unroll
    for (int i = 0; i < 4; i++){
      int linear = tid + i*256;
      int k  = linear >> 5;
      int n4 = linear & 31;
      float4 v = *(const float4*)(W + (size_t)(kk + k)*N + bn + n4*4);
      uint4 u;
      u.x = f2tf32(v.x); u.y = f2tf32(v.y); u.z = f2tf32(v.z); u.w = f2tf32(v.w);
      *(uint4*)(sB + k*132 + n4*4) = u;
    }
    __syncthreads();
    #pragma unroll
    for (int ks = 0; ks < 4; ks++){
      int k0 = ks*8;
      uint32_t a[2][4];
      #pragma unroll
      for (int mf = 0; mf < 2; mf++){
        int row = wm*32 + mf*16 + gid;
        a[mf][0] = sA[(k0 + tidg    )*SA_STRIDE + row];
        a[mf][1] = sA[(k0 + tidg    )*SA_STRIDE + row + 8];
        a[mf][2] = sA[(k0 + tidg + 4)*SA_STRIDE + row];
        a[mf][3] = sA[(k0 + tidg + 4)*SA_STRIDE + row + 8];
      }
      #pragma unroll
      for (int nf = 0; nf < 8; nf++){
        int col = wn*64 + nf*8 + gid;
        uint32_t b0 = sB[(k0 + tidg    )*132 + col];
        uint32_t b1 = sB[(k0 + tidg + 4)*132 + col];
        mma_tf32(acc[nf],     a[0], b0, b1);
        mma_tf32(acc[8 + nf], a[1], b0, b1);
      }
    }
    __syncthreads();
  }
  #pragma unroll
  for (int mf = 0; mf < 2; mf++){
    #pragma unroll
    for (int nf = 0; nf < 8; nf++){
      float* cc = acc[mf*8 + nf];
      int row = bm + wm*32 + mf*16 + gid;
      int col = bn + wn*64 + nf*8 + tidg*2;
      float b0v = bias[col], b1v = bias[col+1];
      float2 v0, v1;
      v0.x = act_apply(cc[0] + b0v, act);
      v0.y = act_apply(cc[1] + b1v, act);
      v1.x = act_apply(cc[2] + b0v, act);
      v1.y = act_apply(cc[3] + b1v, act);
      *(float2*)(C + (size_t)row*N + col)     = v0;
      *(float2*)(C + (size_t)(row+8)*N + col) = v1;
    }
  }
}

// ---------------- persistent bi-LSTM, single-tf32 tensor steps ----------------
// 128 blocks (1/SM): dir(2) x bt(8) x jt(8). Block: 32 batch x (4 gates x 32 hid).
// Whh slice resident in smem as tf32 (converted once). h staged as tf32 (converted once).
#define LSW 136   // sW stride [256][136]
#define LSH 260   // sH stride [32][260]; aliased as sG [32][132]
extern __shared__ float dynsmem[];

__global__ __launch_bounds__(256, 1) void lstm_kernel(
    const float* __restrict__ xgf, const float* __restrict__ xgb,
    const float* __restrict__ Whh_f, const float* __restrict__ Whh_b,
    const float* __restrict__ bhh_f, const float* __restrict__ bhh_b,
    float* __restrict__ hbi)
{
  uint32_t* sW = (uint32_t*)dynsmem;              // [256][LSW] tf32
  uint32_t* sH = (uint32_t*)(dynsmem + 256*LSW);  // [32][LSH] tf32
  float*    sG = dynsmem + 256*LSW;               // alias: [32][132] gate exchange

  int tid = threadIdx.x, blk = blockIdx.x;
  int dir = blk >> 6;
  int bt  = (blk >> 3) & 7;
  int jt  = blk & 7;
  int b0 = bt*32, j0 = jt*32;
  const float* xg  = dir ? xgb   : xgf;
  const float* Whh = dir ? Whh_b : Whh_f;
  const float* bhh = dir ? bhh_b : bhh_f;
  int lane = tid & 31, warp = tid >> 5;
  int gid = lane >> 2, tidg = lane & 3;
  int gW = warp >> 1, nh = warp & 1;
  int colbase = gW*32 + nh*16;
  int ty = tid >> 5, tx = tid & 31;

  // preload Whh slice as tf32: sW[k][g*32+j] = tf32(Whh[k][g*256 + j0 + j])
  for (int idx = tid; idx < 256*128; idx += 256){
    int k = idx >> 7, c = idx & 127, g = c >> 5, j = c & 31;
    sW[k*LSW + c] = f2tf32(Whh[(size_t)k*(4*Hz) + g*Hz + j0 + j]);
  }
  float bh[4];
  #pragma unroll
  for (int g = 0; g < 4; g++) bh[g] = bhh[g*Hz + j0 + tx];
  __syncthreads();

  float c_reg[4] = {0.f,0.f,0.f,0.f};
  unsigned target = 0;

  for (int t = 0; t < TAz; t++){
    int te = dir ? (TAz-1-t) : t;
    float acc[2][2][4];
    #pragma unroll
    for (int mi = 0; mi < 2; mi++)
      #pragma unroll
      for (int ni = 0; ni < 2; ni++)
        #pragma unroll
        for (int q = 0; q < 4; q++) acc[mi][ni][q] = 0.f;

    if (t > 0){
      int tp = dir ? te+1 : te-1;
      // stage h_prev 32x256 as tf32 (one conversion, shared by all warps)
      #pragma unroll
      for (int i = 0; i < 8; i++){
        int idx = tid + i*256;
        int r = idx >> 6, c4 = idx & 63;
        float4 v = __ldcg((const float4*)&hbi[((size_t)(b0+r)*TAz + tp)*512 + dir*Hz + c4*4]);
        uint4 u;
        u.x = f2tf32(v.x); u.y = f2tf32(v.y); u.z = f2tf32(v.z); u.w = f2tf32(v.w);
        *(uint4*)&sH[r*LSH + c4*4] = u;
      }
      __syncthreads();
      #pragma unroll 4
      for (int ks = 0; ks < 32; ks++){
        int k0 = ks*8;
        uint32_t a[2][4];
        #pragma unroll
        for (int mi = 0; mi < 2; mi++){
          int row = mi*16 + gid;
          a[mi][0] = sH[row*LSH + k0 + tidg];
          a[mi][1] = sH[(row+8)*LSH + k0 + tidg];
          a[mi][2] = sH[row*LSH + k0 + tidg + 4];
          a[mi][3] = sH[(row+8)*LSH + k0 + tidg + 4];
        }
        uint32_t b[2][2];
        #pragma unroll
        for (int ni = 0; ni < 2; ni++){
          int col = colbase + ni*8 + gid;
          b[ni][0] = sW[(k0 + tidg)*LSW + col];
          b[ni][1] = sW[(k0 + tidg + 4)*LSW + col];
        }
        #pragma unroll
        for (int mi = 0; mi < 2; mi++)
          #pragma unroll
          for (int ni = 0; ni < 2; ni++)
            mma_tf32(acc[mi][ni], a[mi], b[ni][0], b[ni][1]);
      }
      __syncthreads();   // all warps done reading sH before sG overwrite
    }
    // gate pre-activations -> sG [32][132]
    #pragma unroll
    for (int mi = 0; mi < 2; mi++)
      #pragma unroll
      for (int ni = 0; ni < 2; ni++){
        int r = mi*16 + gid;
        int c = colbase + ni*8 + tidg*2;
        sG[r*132 + c]       = acc[mi][ni][0];
        sG[r*132 + c + 1]   = acc[mi][ni][1];
        sG[(r+8)*132 + c]     = acc[mi][ni][2];
        sG[(r+8)*132 + c + 1] = acc[mi][ni][3];
      }
    __syncthreads();
    // nonlinear update: thread (ty,tx) owns rows ty*4..+3, col tx
    #pragma unroll
    for (int rr = 0; rr < 4; rr++){
      int rloc = ty*4 + rr;
      int b = b0 + rloc;
      size_t base = ((size_t)b*TAz + te)*(4*Hz) + j0 + tx;
      float gi = sG[rloc*132 +  0 + tx] + xg[base + 0*Hz] + bh[0];
      float gf = sG[rloc*132 + 32 + tx] + xg[base + 1*Hz] + bh[1];
      float gg = sG[rloc*132 + 64 + tx] + xg[base + 2*Hz] + bh[2];
      float go = sG[rloc*132 + 96 + tx] + xg[base + 3*Hz] + bh[3];
      float c = sigf(gf)*c_reg[rr] + sigf(gi)*tanhf(gg);
      c_reg[rr] = c;
      hbi[((size_t)b*TAz + te)*512 + dir*Hz + j0 + tx] = sigf(go)*tanhf(c);
    }
    target += 128u;
    gridsync(target);   // also orders sG reads before next step's sH writes
  }
}

// ---------------- persistent GRU, single-tf32 tensor steps ----------------
// 128 blocks (1/SM): bt(8) x jt(16). Block: 32 batch x (3 gates x 32 hid), K=512.
// Register double-buffer for the 4 h_prev chunks; own h tile kept in registers.
#define GSW 104   // sW stride [512][104]
#define GSH 132   // sH/sG stride [32][132]
__global__ __launch_bounds__(256, 1) void gru_kernel(
    const float* __restrict__ xgg, const float* __restrict__ Whh,
    const float* __restrict__ bhh, float* __restrict__ h_out)
{
  uint32_t* sW = (uint32_t*)dynsmem;              // [512][GSW] tf32
  uint32_t* sH = (uint32_t*)(dynsmem + 512*GSW);  // [32][GSH] tf32 chunk
  float*    sG = dynsmem + 512*GSW;               // alias gate exchange

  int tid = threadIdx.x, blk = blockIdx.x;
  int bt = blk >> 4, jt = blk & 15;
  int b0 = bt*32, j0 = jt*32;
  int lane = tid & 31, warp = tid >> 5;
  int gid = lane >> 2, tidg = lane & 3;
  int gW = warp >> 1, nh = warp & 1;       // valid for warp<6
  int colbase = gW*32 + nh*16;
  int ty = tid >> 5, tx = tid & 31;

  // preload Whh slice as tf32: sW[k][g*32+j] = tf32(Whh[k][g*512 + j0 + j])
  for (int idx = tid; idx < 512*96; idx += 256){
    int k = idx / 96, c = idx - k*96;
    int g = c >> 5, j = c & 31;
    sW[k*GSW + c] = f2tf32(Whh[(size_t)k*(3*Dz) + g*Dz + j0 + j]);
  }
  float bh[3];
  #pragma unroll
  for (int g = 0; g < 3; g++) bh[g] = bhh[g*Dz + j0 + tx];
  __syncthreads();

  float hreg[4] = {0.f,0.f,0.f,0.f};   // own h tile (rows ty*4..+3, col tx)
  unsigned target = 0;
  for (int t = 0; t < THz; t++){
    float acc[2][2][4];
    #pragma unroll
    for (int mi = 0; mi < 2; mi++)
      #pragma unroll
      for (int ni = 0; ni < 2; ni++)
        #pragma unroll
        for (int q = 0; q < 4; q++) acc[mi][ni][q] = 0.f;

    if (t > 0){
      uint4 pre[4];
      // preload chunk 0 into registers (tf32-converted)
      #pragma unroll
      for (int i = 0; i < 4; i++){
        int idx = tid + i*256;
        int r = idx >> 5, c4 = idx & 31;
        float4 v = __ldcg((const float4*)&h_out[((size_t)(b0+r)*THz + (t-1))*Dz + 0*128 + c4*4]);
        pre[i].x = f2tf32(v.x); pre[i].y = f2tf32(v.y); pre[i].z = f2tf32(v.z); pre[i].w = f2tf32(v.w);
      }
      for (int cc = 0; cc < 4; cc++){
        __syncthreads();                 // previous readers of sH done
        #pragma unroll
        for (int i = 0; i < 4; i++){
          int idx = tid + i*256;
          int r = idx >> 5, c4 = idx & 31;
          *(uint4*)&sH[r*GSH + c4*4] = pre[i];
        }
        if (cc < 3){                     // prefetch next chunk; hidden under MMA phase
          #pragma unroll
          for (int i = 0; i < 4; i++){
            int idx = tid + i*256;
            int r = idx >> 5, c4 = idx & 31;
            float4 v = __ldcg((const float4*)&h_out[((size_t)(b0+r)*THz + (t-1))*Dz + (cc+1)*128 + c4*4]);
            pre[i].x = f2tf32(v.x); pre[i].y = f2tf32(v.y); pre[i].z = f2tf32(v.z); pre[i].w = f2tf32(v.w);
          }
        }
        __syncthreads();
        if (warp < 6){
          #pragma unroll 4
          for (int ks = 0; ks < 16; ks++){
            int k0 = ks*8;
            uint32_t a[2][4];
            #pragma unroll
            for (int mi = 0; mi < 2; mi++){
              int row = mi*16 + gid;
              a[mi][0] = sH[row*GSH + k0 + tidg];
              a[mi][1] = sH[(row+8)*GSH + k0 + tidg];
              a[mi][2] = sH[row*GSH + k0 + tidg + 4];
              a[mi][3] = sH[(row+8)*GSH + k0 + tidg + 4];
            }
            uint32_t b[2][2];
            #pragma unroll
            for (int ni = 0; ni < 2; ni++){
              int col = colbase + ni*8 + gid;
              int krow = cc*128 + k0 + tidg;
              b[ni][0] = sW[krow*GSW + col];
              b[ni][1] = sW[(krow + 4)*GSW + col];
            }
            #pragma unroll
            for (int mi = 0; mi < 2; mi++)
              #pragma unroll
              for (int ni = 0; ni < 2; ni++)
                mma_tf32(acc[mi][ni], a[mi], b[ni][0], b[ni][1]);
          }
        }
      }
      __syncthreads();                   // last MMA done before sG overwrite
    }
    // gate pre-activations -> sG (cols: g*32 + j, g in {r,z,n})
    if (warp < 6){
      #pragma unroll
      for (int mi = 0; mi < 2; mi++)
        #pragma unroll
        for (int ni = 0; ni < 2; ni++){
          int r = mi*16 + gid;
          int c = colbase + ni*8 + tidg*2;
          sG[r*GSH + c]       = acc[mi][ni][0];
          sG[r*GSH + c + 1]   = acc[mi][ni][1];
          sG[(r+8)*GSH + c]     = acc[mi][ni][2];
          sG[(r+8)*GSH + c + 1] = acc[mi][ni][3];
        }
    }
    __syncthreads();
    #pragma unroll
    for (int rr = 0; rr < 4; rr++){
      int rloc = ty*4 + rr;
      int b = b0 + rloc;
      size_t xbase = ((size_t)b*THz + t)*(3*Dz) + j0 + tx;
      float xr = xgg[xbase + 0*Dz], xz = xgg[xbase + 1*Dz], xn = xgg[xbase + 2*Dz];
      float hr = sG[rloc*GSH +  0 + tx];
      float hz = sG[rloc*GSH + 32 + tx];
      float hn = sG[rloc*GSH + 64 + tx];
      float r = sigf(xr + hr + bh[0]);
      float z = sigf(xz + hz + bh[1]);
      float n = tanhf(xn + r*(hn + bh[2]));
      float h = (1.f - z)*n + z*hreg[rr];
      hreg[rr] = h;
      h_out[((size_t)b*THz + t)*Dz + j0 + tx] = h;
    }
    target += 128u;
    gridsync(target);
  }
}

// ---------------- fold W_e2 @ W_head into one vector + scalar ----------------
__global__ void w2h_kernel(const float* __restrict__ W_e2, const float* __restrict__ b_e2,
                           const float* __restrict__ W_head, const float* __restrict__ b_head)
{
  int tid = threadIdx.x;
  for (int d = tid; d < Dz; d += 256){
    float s = 0.f;
    for (int j = 0; j < Dz; j++) s += W_e2[(size_t)d*Dz + j]*W_head[j];
    g_w2h[d] = s;
  }
  if (tid == 0){
    float s = 0.f;
    for (int j = 0; j < Dz; j++) s += b_e2[j]*W_head[j];
    g_w2h[Dz] = s + b_head[0];
  }
}

// ---------------- build cat = [h_seq, qm + qs*eps] ----------------
__global__ __launch_bounds__(256) void cat_kernel(
    const float* __restrict__ h, const float* __restrict__ qm,
    const float* __restrict__ qs, const float* __restrict__ eps,
    float* __restrict__ cat)
{
  int row = blockIdx.x;               // b*TH + t
  int tid = threadIdx.x;
  float* dst = cat + (size_t)row*(Dz+Lz);
  const float* hs = h + (size_t)row*Dz;
  for (int i = tid; i < Dz; i += 256) dst[i] = hs[i];
  int b = row >> 9, t = row & 511;
  size_t q = ((size_t)b*TAz + t)*Lz;
  size_t e = (size_t)row*Lz;
  for (int i = tid; i < Lz; i += 256) dst[Dz+i] = qm[q+i] + qs[q+i]*eps[e+i];
}

// ---------------- y = gelu_out @ w2h + c2 ----------------
__global__ __launch_bounds__(256) void y_kernel(const float* __restrict__ gel,
                                                float* __restrict__ out_y)
{
  __shared__ float sw[Dz];
  __shared__ float c2s;
  int tid = threadIdx.x;
  for (int i = tid; i < Dz; i += 256) sw[i] = g_w2h[i];
  if (tid == 0) c2s = g_w2h[Dz];
  __syncthreads();
  int lane = tid & 31;
  int warp = (blockIdx.x*blockDim.x + tid) >> 5;
  int nwarp = (gridDim.x*blockDim.x) >> 5;
  for (int row = warp; row < Bz*THz; row += nwarp){
    const float* g = gel + (size_t)row*Dz;
    float s = 0.f;
    #pragma unroll
    for (int i = 0; i < Dz/32; i++) s += g[lane + i*32]*sw[lane + i*32];
    #pragma unroll
    for (int o = 16; o; o >>= 1) s += __shfl_xor_sync(0xffffffffu, s, o);
    if (lane == 0) out_y[row] = s + c2s;
  }
}

// ---------------- launch ----------------
extern "C" void kernel_launch(void* const* d_in, const int* in_sizes, int n_in,
                              void* d_out, int out_size)
{
  (void)in_sizes; (void)n_in; (void)out_size;
  const float* patches_hist = (const float*)d_in[0];
  const float* patches_all  = (const float*)d_in[1];
  const float* eps    = (const float*)d_in[2];
  const float* W_embed= (const float*)d_in[3];
  const float* b_embed= (const float*)d_in[4];
  const float* Wih_f  = (const float*)d_in[5];
  const float* Whh_f  = (const float*)d_in[6];
  const float* bih_f  = (const float*)d_in[7];
  const float* bhh_f  = (const float*)d_in[8];
  const float* Wih_b  = (const float*)d_in[9];
  const float* Whh_b  = (const float*)d_in[10];
  const float* bih_b  = (const float*)d_in[11];
  const float* bhh_b  = (const float*)d_in[12];
  const float* Wqm    = (const float*)d_in[13];
  const float* bqm    = (const float*)d_in[14];
  const float* Wqs    = (const float*)d_in[15];
  const float* bqs    = (const float*)d_in[16];
  const float* Wih_g  = (const float*)d_in[17];
  const float* Whh_g  = (const float*)d_in[18];
  const float* bih_g  = (const float*)d_in[19];
  const float* bhh_g  = (const float*)d_in[20];
  const float* Wpm    = (const float*)d_in[21];
  const float* bpm    = (const float*)d_in[22];
  const float* Wps    = (const float*)d_in[23];
  const float* bps    = (const float*)d_in[24];
  const float* W_e1   = (const float*)d_in[25];
  const float* b_e1   = (const float*)d_in[26];
  const float* W_e2   = (const float*)d_in[27];
  const float* b_e2   = (const float*)d_in[28];
  const float* W_head = (const float*)d_in[29];
  const float* b_head = (const float*)d_in[30];
  float* out = (float*)d_out;

  // output layout: y_hist, prior_m, prior_s, qm_all, qs_all, h_seq (flattened, concatenated)
  float* out_y  = out + 0;
  float* out_pm = out + 131072;
  float* out_ps = out + 16908288;
  float* out_qm = out + 33685504;
  float* out_qs = out + 52559872;
  float* out_h  = out + 71434240;

  float *x_hist, *x_all, *xgf, *xgb, *xgg, *hbi;
  cudaGetSymbolAddress((void**)&x_hist, g_x_hist);
  cudaGetSymbolAddress((void**)&x_all,  g_x_all);
  cudaGetSymbolAddress((void**)&xgf,    g_xgf);
  cudaGetSymbolAddress((void**)&xgb,    g_xgb);
  cudaGetSymbolAddress((void**)&xgg,    g_xgg);
  cudaGetSymbolAddress((void**)&hbi,    g_hbi);
  float* cat = xgf;     // reuse: xgf dead after LSTM steps
  float* gel = x_all;   // reuse: x_all dead after xg GEMMs

  const int LSTM_SMEM = (256*LSW + 32*LSH)*4;   // 172,544 B
  const int GRU_SMEM  = (512*GSW + 32*GSH)*4;   // 229,888 B
  static int attr_done = 0;
  if (!attr_done){
    cudaFuncSetAttribute(lstm_kernel, cudaFuncAttributeMaxDynamicSharedMemorySize, LSTM_SMEM);
    cudaFuncSetAttribute(gru_kernel,  cudaFuncAttributeMaxDynamicSharedMemorySize, GRU_SMEM);
    attr_done = 1;
  }

  // 1. embed
  embed_kernel<<<(Bz*TAz)/64, 256>>>(patches_all,  W_embed, b_embed, x_all);
  embed_kernel<<<(Bz*THz)/64, 256>>>(patches_hist, W_embed, b_embed, x_hist);

  // 2. input-gate GEMMs (tf32 mma.sync)
  tgemm_kernel<<<dim3(1024/128, (Bz*TAz)/128), 256>>>(x_all,  Wih_f, bih_f, xgf, Bz*TAz, 1024, 512, 0);
  tgemm_kernel<<<dim3(1024/128, (Bz*TAz)/128), 256>>>(x_all,  Wih_b, bih_b, xgb, Bz*TAz, 1024, 512, 0);
  tgemm_kernel<<<dim3(1536/128, (Bz*THz)/128), 256>>>(x_hist, Wih_g, bih_g, xgg, Bz*THz, 1536, 512, 0);

  // 3. recurrences: persistent tensor-core kernels, software grid barrier
  reset_bar_kernel<<<1,1>>>();
  lstm_kernel<<<128,256,LSTM_SMEM>>>(xgf, xgb, Whh_f, Whh_b, bhh_f, bhh_b, hbi);
  reset_bar_kernel<<<1,1>>>();
  gru_kernel<<<128,256,GRU_SMEM>>>(xgg, Whh_g, bhh_g, out_h);

  // 4. posterior / prior heads (tf32 mma.sync)
  tgemm_kernel<<<dim3(1, (Bz*TAz)/128), 256>>>(hbi,   Wqm, bqm, out_qm, Bz*TAz, 128, 512, 0);
  tgemm_kernel<<<dim3(1, (Bz*TAz)/128), 256>>>(hbi,   Wqs, bqs, out_qs, Bz*TAz, 128, 512, 1);
  tgemm_kernel<<<dim3(1, (Bz*THz)/128), 256>>>(out_h, Wpm, bpm, out_pm, Bz*THz, 128, 512, 0);
  tgemm_kernel<<<dim3(1, (Bz*THz)/128), 256>>>(out_h, Wps, bps, out_ps, Bz*THz, 128, 512, 1);

  // 5. emission (head folded: y = gelu(cat@W_e1+b_e1) @ (W_e2@W_head) + (b_e2@W_head + b_head))
  w2h_kernel<<<1,256>>>(W_e2, b_e2, W_head, b_head);
  cat_kernel<<<Bz*THz, 256>>>(out_h, out_qm, out_qs, eps, cat);
  tgemm_kernel<<<dim3(512/128, (Bz*THz)/128), 256>>>(cat, W_e1, b_e1, gel, Bz*THz, 512, 640, 2);
  y_kernel<<<2048,256>>>(gel, out_y);
}

// round 17
// speedup vs baseline: 2.6007x; 1.1161x over previous
#include <cuda_runtime.h>
#include <cstdint>

#define Bz  256
#define THz 512
#define TAz 576
#define Pz  16
#define Dz  512
#define Lz  128
#define Hz  256

// ---------------- scratch (static device globals; no allocation) ----------------
__device__ float g_x_hist[Bz*THz*Dz];          // [B,TH,D]
__device__ float g_x_all [Bz*TAz*Dz];          // [B,TA,D]; reused later as gelu output [B,TH,D]
__device__ float g_xgf   [Bz*TAz*4*Hz];        // [B,TA,4H]; reused later as cat [B,TH,D+L]
__device__ float g_xgb   [Bz*TAz*4*Hz];
__device__ float g_xgg   [Bz*THz*3*Dz];        // [B,TH,3D]
__device__ float g_hbi   [Bz*TAz*Dz];          // [B,TA,2H] (hf | hb)
__device__ float g_w2h   [Dz+1];               // W_e2@W_head, plus scalar c2 at [Dz]
__device__ unsigned g_bars[16*32];             // per-group barrier counters, 128B apart

// ---------------- helpers ----------------
__device__ __forceinline__ float sigf(float x){ return 1.f/(1.f+expf(-x)); }

__device__ __forceinline__ float act_apply(float v, int act){
  if (act == 1){                      // softplus + 1e-5 (stable logaddexp(x,0))
    v = fmaxf(v, 0.f) + log1pf(expf(-fabsf(v))) + 1e-5f;
  } else if (act == 2){               // exact GELU
    v = 0.5f*v*(1.f + erff(v*0.7071067811865476f));
  }
  return v;
}

__device__ __forceinline__ uint32_t f2tf32(float f){
  uint32_t u; asm("cvt.rna.tf32.f32 %0, %1;" : "=r"(u) : "f"(f)); return u;
}

// m16n8k8 tf32 MMA (legacy tensor path; plain-PTX, works on sm_103 target)
__device__ __forceinline__ void mma_tf32(float* c, const uint32_t* a, uint32_t b0, uint32_t b1){
  asm volatile("mma.sync.aligned.m16n8k8.row.col.f32.tf32.tf32.f32 "
      "{%0,%1,%2,%3}, {%4,%5,%6,%7}, {%8,%9}, {%0,%1,%2,%3};"
      : "+f"(c[0]), "+f"(c[1]), "+f"(c[2]), "+f"(c[3])
      : "r"(a[0]), "r"(a[1]), "r"(a[2]), "r"(a[3]), "r"(b0), "r"(b1));
}

__device__ __forceinline__ void cpasync16(uint32_t dst, const void* src){
  asm volatile("cp.async.cg.shared.global [%0], [%1], 16;" :: "r"(dst), "l"(src));
}
#define CP_COMMIT() asm volatile("cp.async.commit_group;" ::: "memory")
#define CP_WAIT1()  asm volatile("cp.async.wait_group 1;" ::: "memory")
#define CP_WAIT0()  asm volatile("cp.async.wait_group 0;" ::: "memory")

__device__ __forceinline__ uint32_t smem_u32(const void* p) {
  uint32_t a;
  asm("{ .reg .u64 t; cvta.to.shared.u64 t, %1; cvt.u32.u64 %0, t; }" : "=r"(a) : "l"(p));
  return a;
}

// group-local barrier among `cnt` blocks sharing counter `ctr`
__device__ __forceinline__ void groupsync(unsigned* ctr, unsigned target){
  __threadfence();
  __syncthreads();
  if (threadIdx.x == 0){
    atomicAdd(ctr, 1u);
    long long start = clock64();
    unsigned v;
    do {
      asm volatile("ld.global.cg.u32 %0, [%1];" : "=r"(v) : "l"(ctr));
      if (v >= target) break;
      __nanosleep(32);
    } while (clock64() - start < 40000000000LL);
    __threadfence();
  }
  __syncthreads();
}

__global__ void reset_bar_kernel(){
  if (threadIdx.x < 16) g_bars[threadIdx.x*32] = 0u;
}

// ---------------- embed: X = patches @ W_embed + b ----------------
__global__ __launch_bounds__(256) void embed_kernel(
    const float* __restrict__ patches, const float* __restrict__ W,
    const float* __restrict__ bias, float* __restrict__ X)
{
  __shared__ float sW[Pz*Dz];
  __shared__ float sb[Dz];
  __shared__ float sP[64*Pz];
  int tid = threadIdx.x;
  for (int i = tid; i < Pz*Dz; i += 256) sW[i] = W[i];
  for (int i = tid; i < Dz;    i += 256) sb[i] = bias[i];
  size_t r0 = (size_t)blockIdx.x * 64;
  for (int i = tid; i < 64*Pz; i += 256) sP[i] = patches[r0*Pz + i];
  __syncthreads();
  for (int rr = 0; rr < 64; rr++){
    const float* pv = sP + rr*Pz;
    #pragma unroll
    for (int half = 0; half < 2; half++){
      int d = tid + half*256;
      float acc = sb[d];
      #pragma unroll
      for (int p = 0; p < Pz; p++) acc += pv[p]*sW[p*Dz + d];
      X[(r0+rr)*Dz + d] = acc;
    }
  }
}

// ---------------- tf32 mma.sync GEMM, cp.async double-buffered ----------------
// grid (N/128, M/128), 256 threads = 8 warps (4m x 2n), warp tile 32x64, BK=32.
// A raw [m][k] stride 36 (conflict-free fragments), B raw [k][n] stride 132.
#define SAR 36
#define SBR 132
#define TG_STG (128*SAR + 32*SBR)          // floats per stage = 8832
#define TG_SMEM (2*TG_STG*4)               // 70,656 B
extern __shared__ float dynsmem[];

__global__ __launch_bounds__(256) void tgemm_kernel(
    const float* __restrict__ A, const float* __restrict__ W,
    const float* __restrict__ bias, float* __restrict__ C,
    int M, int N, int K, int act)
{
  int tid = threadIdx.x;
  int lane = tid & 31, warp = tid >> 5;
  int wm = warp & 3, wn = warp >> 2;
  int gid = lane >> 2, tidg = lane & 3;
  int bm = blockIdx.y*128, bn = blockIdx.x*128;

  uint32_t sbase = smem_u32(dynsmem);
  int ar = tid >> 3, ac4 = tid & 7;        // A chunks: rows ar+i*32, col-quad ac4
  int bk = tid >> 5, bn4 = tid & 31;       // B chunks: k bk+i*8, col-quad bn4

  float acc[16][4];
  #pragma unroll
  for (int i = 0; i < 16; i++)
    #pragma unroll
    for (int j = 0; j < 4; j++) acc[i][j] = 0.f;

  int nch = K >> 5;

  // issue chunk 0 into stage 0
  {
    uint32_t abase = sbase, bbase = sbase + 128*SAR*4;
    #pragma unroll
    for (int i = 0; i < 4; i++){
      int r = ar + i*32;
      cpasync16(abase + (r*SAR + ac4*4)*4, A + (size_t)(bm + r)*K + ac4*4);
    }
    #pragma unroll
    for (int i = 0; i < 4; i++){
      int k = bk + i*8;
      cpasync16(bbase + (k*SBR + bn4*4)*4, W + (size_t)k*N + bn + bn4*4);
    }
    CP_COMMIT();
  }

  for (int ch = 0; ch < nch; ch++){
    int st = ch & 1;
    if (ch + 1 < nch){
      uint32_t abase = sbase + (st^1)*TG_STG*4;
      uint32_t bbase = abase + 128*SAR*4;
      int kk = (ch+1) << 5;
      #pragma unroll
      for (int i = 0; i < 4; i++){
        int r = ar + i*32;
        cpasync16(abase + (r*SAR + ac4*4)*4, A + (size_t)(bm + r)*K + kk + ac4*4);
      }
      #pragma unroll
      for (int i = 0; i < 4; i++){
        int k = bk + i*8;
        cpasync16(bbase + (k*SBR + bn4*4)*4, W + (size_t)(kk + k)*N + bn + bn4*4);
      }
      CP_COMMIT();
      CP_WAIT1();
    } else {
      CP_WAIT0();
    }
    __syncthreads();
    // in-place fp32 -> tf32 convert of stage st
    float* aS = dynsmem + st*TG_STG;
    float* bS = aS + 128*SAR;
    #pragma unroll
    for (int i = 0; i < 4; i++){
      float4* p = (float4*)(aS + (ar + i*32)*SAR + ac4*4);
      float4 v = *p;
      uint4 u; u.x = f2tf32(v.x); u.y = f2tf32(v.y); u.z = f2tf32(v.z); u.w = f2tf32(v.w);
      *(uint4*)p = u;
    }
    #pragma unroll
    for (int i = 0; i < 4; i++){
      float4* p = (float4*)(bS + (bk + i*8)*SBR + bn4*4);
      float4 v = *p;
      uint4 u; u.x = f2tf32(v.x); u.y = f2tf32(v.y); u.z = f2tf32(v.z); u.w = f2tf32(v.w);
      *(uint4*)p = u;
    }
    __syncthreads();
    // MMA phase
    uint32_t* sA = (uint32_t*)aS;
    uint32_t* sB = (uint32_t*)bS;
    #pragma unroll
    for (int ks = 0; ks < 4; ks++){
      int k0 = ks*8;
      uint32_t a[2][4];
      #pragma unroll
      for (int mf = 0; mf < 2; mf++){
        int row = wm*32 + mf*16 + gid;
        a[mf][0] = sA[row*SAR + k0 + tidg];
        a[mf][1] = sA[(row+8)*SAR + k0 + tidg];
        a[mf][2] = sA[row*SAR + k0 + tidg + 4];
        a[mf][3] = sA[(row+8)*SAR + k0 + tidg + 4];
      }
      #pragma unroll
      for (int nf = 0; nf < 8; nf++){
        int col = wn*64 + nf*8 + gid;
        uint32_t b0 = sB[(k0 + tidg    )*SBR + col];
        uint32_t b1 = sB[(k0 + tidg + 4)*SBR + col];
        mma_tf32(acc[nf],     a[0], b0, b1);
        mma_tf32(acc[8 + nf], a[1], b0, b1);
      }
    }
    __syncthreads();
  }
  // epilogue: fused bias + activation
  #pragma unroll
  for (int mf = 0; mf < 2; mf++){
    #pragma unroll
    for (int nf = 0; nf < 8; nf++){
      float* cc = acc[mf*8 + nf];
      int row = bm + wm*32 + mf*16 + gid;
      int col = bn + wn*64 + nf*8 + tidg*2;
      float b0v = bias[col], b1v = bias[col+1];
      float2 v0, v1;
      v0.x = act_apply(cc[0] + b0v, act);
      v0.y = act_apply(cc[1] + b1v, act);
      v1.x = act_apply(cc[2] + b0v, act);
      v1.y = act_apply(cc[3] + b1v, act);
      *(float2*)(C + (size_t)row*N + col)     = v0;
      *(float2*)(C + (size_t)(row+8)*N + col) = v1;
    }
  }
}

// ---------------- persistent bi-LSTM, single-tf32 tensor steps ----------------
// 128 blocks (1/SM): dir(2) x bt(8) x jt(8). Group barrier = 8 blocks of (dir,bt).
#define LSW 136
#define LSH 260
__global__ __launch_bounds__(256, 1) void lstm_kernel(
    const float* __restrict__ xgf, const float* __restrict__ xgb,
    const float* __restrict__ Whh_f, const float* __restrict__ Whh_b,
    const float* __restrict__ bhh_f, const float* __restrict__ bhh_b,
    float* __restrict__ hbi)
{
  uint32_t* sW = (uint32_t*)dynsmem;              // [256][LSW] tf32
  uint32_t* sH = (uint32_t*)(dynsmem + 256*LSW);  // [32][LSH] tf32
  float*    sG = dynsmem + 256*LSW;               // alias: [32][132] gate exchange

  int tid = threadIdx.x, blk = blockIdx.x;
  int dir = blk >> 6;
  int bt  = (blk >> 3) & 7;
  int jt  = blk & 7;
  int b0 = bt*32, j0 = jt*32;
  const float* xg  = dir ? xgb   : xgf;
  const float* Whh = dir ? Whh_b : Whh_f;
  const float* bhh = dir ? bhh_b : bhh_f;
  int lane = tid & 31, warp = tid >> 5;
  int gid = lane >> 2, tidg = lane & 3;
  int gW = warp >> 1, nh = warp & 1;
  int colbase = gW*32 + nh*16;
  int ty = tid >> 5, tx = tid & 31;
  unsigned* ctr = &g_bars[(dir*8 + bt)*32];

  for (int idx = tid; idx < 256*128; idx += 256){
    int k = idx >> 7, c = idx & 127, g = c >> 5, j = c & 31;
    sW[k*LSW + c] = f2tf32(Whh[(size_t)k*(4*Hz) + g*Hz + j0 + j]);
  }
  float bh[4];
  #pragma unroll
  for (int g = 0; g < 4; g++) bh[g] = bhh[g*Hz + j0 + tx];
  __syncthreads();

  float c_reg[4] = {0.f,0.f,0.f,0.f};
  float xgr[4][4];
  // prefetch xg for t=0
  {
    int te = dir ? (TAz-1) : 0;
    #pragma unroll
    for (int rr = 0; rr < 4; rr++){
      size_t base = ((size_t)(b0 + ty*4 + rr)*TAz + te)*(4*Hz) + j0 + tx;
      #pragma unroll
      for (int g = 0; g < 4; g++) xgr[rr][g] = xg[base + g*Hz];
    }
  }
  unsigned target = 0;

  for (int t = 0; t < TAz; t++){
    int te = dir ? (TAz-1-t) : t;
    float acc[2][2][4];
    #pragma unroll
    for (int mi = 0; mi < 2; mi++)
      #pragma unroll
      for (int ni = 0; ni < 2; ni++)
        #pragma unroll
        for (int q = 0; q < 4; q++) acc[mi][ni][q] = 0.f;

    if (t > 0){
      int tp = dir ? te+1 : te-1;
      #pragma unroll
      for (int i = 0; i < 8; i++){
        int idx = tid + i*256;
        int r = idx >> 6, c4 = idx & 63;
        float4 v = __ldcg((const float4*)&hbi[((size_t)(b0+r)*TAz + tp)*512 + dir*Hz + c4*4]);
        uint4 u;
        u.x = f2tf32(v.x); u.y = f2tf32(v.y); u.z = f2tf32(v.z); u.w = f2tf32(v.w);
        *(uint4*)&sH[r*LSH + c4*4] = u;
      }
      __syncthreads();
      #pragma unroll 4
      for (int ks = 0; ks < 32; ks++){
        int k0 = ks*8;
        uint32_t a[2][4];
        #pragma unroll
        for (int mi = 0; mi < 2; mi++){
          int row = mi*16 + gid;
          a[mi][0] = sH[row*LSH + k0 + tidg];
          a[mi][1] = sH[(row+8)*LSH + k0 + tidg];
          a[mi][2] = sH[row*LSH + k0 + tidg + 4];
          a[mi][3] = sH[(row+8)*LSH + k0 + tidg + 4];
        }
        uint32_t b[2][2];
        #pragma unroll
        for (int ni = 0; ni < 2; ni++){
          int col = colbase + ni*8 + gid;
          b[ni][0] = sW[(k0 + tidg)*LSW + col];
          b[ni][1] = sW[(k0 + tidg + 4)*LSW + col];
        }
        #pragma unroll
        for (int mi = 0; mi < 2; mi++)
          #pragma unroll
          for (int ni = 0; ni < 2; ni++)
            mma_tf32(acc[mi][ni], a[mi], b[ni][0], b[ni][1]);
      }
      __syncthreads();
    }
    #pragma unroll
    for (int mi = 0; mi < 2; mi++)
      #pragma unroll
      for (int ni = 0; ni < 2; ni++){
        int r = mi*16 + gid;
        int c = colbase + ni*8 + tidg*2;
        sG[r*132 + c]       = acc[mi][ni][0];
        sG[r*132 + c + 1]   = acc[mi][ni][1];
        sG[(r+8)*132 + c]     = acc[mi][ni][2];
        sG[(r+8)*132 + c + 1] = acc[mi][ni][3];
      }
    __syncthreads();
    #pragma unroll
    for (int rr = 0; rr < 4; rr++){
      int rloc = ty*4 + rr;
      int b = b0 + rloc;
      float gi = sG[rloc*132 +  0 + tx] + xgr[rr][0] + bh[0];
      float gf = sG[rloc*132 + 32 + tx] + xgr[rr][1] + bh[1];
      float gg = sG[rloc*132 + 64 + tx] + xgr[rr][2] + bh[2];
      float go = sG[rloc*132 + 96 + tx] + xgr[rr][3] + bh[3];
      float c = sigf(gf)*c_reg[rr] + sigf(gi)*tanhf(gg);
      c_reg[rr] = c;
      hbi[((size_t)b*TAz + te)*512 + dir*Hz + j0 + tx] = sigf(go)*tanhf(c);
    }
    if (t + 1 < TAz){
      int te2 = dir ? (TAz-2-t) : t+1;
      #pragma unroll
      for (int rr = 0; rr < 4; rr++){
        size_t base = ((size_t)(b0 + ty*4 + rr)*TAz + te2)*(4*Hz) + j0 + tx;
        #pragma unroll
        for (int g = 0; g < 4; g++) xgr[rr][g] = xg[base + g*Hz];
      }
    }
    target += 8u;
    groupsync(ctr, target);
  }
}

// ---------------- persistent GRU, single-tf32 tensor steps ----------------
// 128 blocks (1/SM): bt(8) x jt(16). Group barrier = 16 blocks of bt.
#define GSW 104
#define GSH 132
__global__ __launch_bounds__(256, 1) void gru_kernel(
    const float* __restrict__ xgg, const float* __restrict__ Whh,
    const float* __restrict__ bhh, float* __restrict__ h_out)
{
  uint32_t* sW = (uint32_t*)dynsmem;              // [512][GSW] tf32
  uint32_t* sH = (uint32_t*)(dynsmem + 512*GSW);  // [32][GSH] tf32 chunk
  float*    sG = dynsmem + 512*GSW;               // alias gate exchange

  int tid = threadIdx.x, blk = blockIdx.x;
  int bt = blk >> 4, jt = blk & 15;
  int b0 = bt*32, j0 = jt*32;
  int lane = tid & 31, warp = tid >> 5;
  int gid = lane >> 2, tidg = lane & 3;
  int gW = warp >> 1, nh = warp & 1;       // valid for warp<6
  int colbase = gW*32 + nh*16;
  int ty = tid >> 5, tx = tid & 31;
  unsigned* ctr = &g_bars[bt*32];

  for (int idx = tid; idx < 512*96; idx += 256){
    int k = idx / 96, c = idx - k*96;
    int g = c >> 5, j = c & 31;
    sW[k*GSW + c] = f2tf32(Whh[(size_t)k*(3*Dz) + g*Dz + j0 + j]);
  }
  float bh[3];
  #pragma unroll
  for (int g = 0; g < 3; g++) bh[g] = bhh[g*Dz + j0 + tx];
  __syncthreads();

  float hreg[4] = {0.f,0.f,0.f,0.f};
  float xgr[4][3];
  #pragma unroll
  for (int rr = 0; rr < 4; rr++){
    size_t base = ((size_t)(b0 + ty*4 + rr)*THz + 0)*(3*Dz) + j0 + tx;
    #pragma unroll
    for (int g = 0; g < 3; g++) xgr[rr][g] = xgg[base + g*Dz];
  }
  unsigned target = 0;
  for (int t = 0; t < THz; t++){
    float acc[2][2][4];
    #pragma unroll
    for (int mi = 0; mi < 2; mi++)
      #pragma unroll
      for (int ni = 0; ni < 2; ni++)
        #pragma unroll
        for (int q = 0; q < 4; q++) acc[mi][ni][q] = 0.f;

    if (t > 0){
      uint4 pre[4];
      #pragma unroll
      for (int i = 0; i < 4; i++){
        int idx = tid + i*256;
        int r = idx >> 5, c4 = idx & 31;
        float4 v = __ldcg((const float4*)&h_out[((size_t)(b0+r)*THz + (t-1))*Dz + c4*4]);
        pre[i].x = f2tf32(v.x); pre[i].y = f2tf32(v.y); pre[i].z = f2tf32(v.z); pre[i].w = f2tf32(v.w);
      }
      for (int cc = 0; cc < 4; cc++){
        __syncthreads();
        #pragma unroll
        for (int i = 0; i < 4; i++){
          int idx = tid + i*256;
          int r = idx >> 5, c4 = idx & 31;
          *(uint4*)&sH[r*GSH + c4*4] = pre[i];
        }
        if (cc < 3){
          #pragma unroll
          for (int i = 0; i < 4; i++){
            int idx = tid + i*256;
            int r = idx >> 5, c4 = idx & 31;
            float4 v = __ldcg((const float4*)&h_out[((size_t)(b0+r)*THz + (t-1))*Dz + (cc+1)*128 + c4*4]);
            pre[i].x = f2tf32(v.x); pre[i].y = f2tf32(v.y); pre[i].z = f2tf32(v.z); pre[i].w = f2tf32(v.w);
          }
        }
        __syncthreads();
        if (warp < 6){
          #pragma unroll 4
          for (int ks = 0; ks < 16; ks++){
            int k0 = ks*8;
            uint32_t a[2][4];
            #pragma unroll
            for (int mi = 0; mi < 2; mi++){
              int row = mi*16 + gid;
              a[mi][0] = sH[row*GSH + k0 + tidg];
              a[mi][1] = sH[(row+8)*GSH + k0 + tidg];
              a[mi][2] = sH[row*GSH + k0 + tidg + 4];
              a[mi][3] = sH[(row+8)*GSH + k0 + tidg + 4];
            }
            uint32_t b[2][2];
            #pragma unroll
            for (int ni = 0; ni < 2; ni++){
              int col = colbase + ni*8 + gid;
              int krow = cc*128 + k0 + tidg;
              b[ni][0] = sW[krow*GSW + col];
              b[ni][1] = sW[(krow + 4)*GSW + col];
            }
            #pragma unroll
            for (int mi = 0; mi < 2; mi++)
              #pragma unroll
              for (int ni = 0; ni < 2; ni++)
                mma_tf32(acc[mi][ni], a[mi], b[ni][0], b[ni][1]);
          }
        }
      }
      __syncthreads();
    }
    if (warp < 6){
      #pragma unroll
      for (int mi = 0; mi < 2; mi++)
        #pragma unroll
        for (int ni = 0; ni < 2; ni++){
          int r = mi*16 + gid;
          int c = colbase + ni*8 + tidg*2;
          sG[r*GSH + c]       = acc[mi][ni][0];
          sG[r*GSH + c + 1]   = acc[mi][ni][1];
          sG[(r+8)*GSH + c]     = acc[mi][ni][2];
          sG[(r+8)*GSH + c + 1] = acc[mi][ni][3];
        }
    }
    __syncthreads();
    #pragma unroll
    for (int rr = 0; rr < 4; rr++){
      int rloc = ty*4 + rr;
      int b = b0 + rloc;
      float r = sigf(xgr[rr][0] + sG[rloc*GSH +  0 + tx] + bh[0]);
      float z = sigf(xgr[rr][1] + sG[rloc*GSH + 32 + tx] + bh[1]);
      float n = tanhf(xgr[rr][2] + r*(sG[rloc*GSH + 64 + tx] + bh[2]));
      float h = (1.f - z)*n + z*hreg[rr];
      hreg[rr] = h;
      h_out[((size_t)b*THz + t)*Dz + j0 + tx] = h;
    }
    if (t + 1 < THz){
      #pragma unroll
      for (int rr = 0; rr < 4; rr++){
        size_t base = ((size_t)(b0 + ty*4 + rr)*THz + (t+1))*(3*Dz) + j0 + tx;
        #pragma unroll
        for (int g = 0; g < 3; g++) xgr[rr][g] = xgg[base + g*Dz];
      }
    }
    target += 16u;
    groupsync(ctr, target);
  }
}

// ---------------- fold W_e2 @ W_head into one vector + scalar ----------------
__global__ void w2h_kernel(const float* __restrict__ W_e2, const float* __restrict__ b_e2,
                           const float* __restrict__ W_head, const float* __restrict__ b_head)
{
  int tid = threadIdx.x;
  for (int d = tid; d < Dz; d += 256){
    float s = 0.f;
    for (int j = 0; j < Dz; j++) s += W_e2[(size_t)d*Dz + j]*W_head[j];
    g_w2h[d] = s;
  }
  if (tid == 0){
    float s = 0.f;
    for (int j = 0; j < Dz; j++) s += b_e2[j]*W_head[j];
    g_w2h[Dz] = s + b_head[0];
  }
}

// ---------------- build cat = [h_seq, qm + qs*eps] ----------------
__global__ __launch_bounds__(256) void cat_kernel(
    const float* __restrict__ h, const float* __restrict__ qm,
    const float* __restrict__ qs, const float* __restrict__ eps,
    float* __restrict__ cat)
{
  int row = blockIdx.x;               // b*TH + t
  int tid = threadIdx.x;
  float* dst = cat + (size_t)row*(Dz+Lz);
  const float* hs = h + (size_t)row*Dz;
  for (int i = tid; i < Dz; i += 256) dst[i] = hs[i];
  int b = row >> 9, t = row & 511;
  size_t q = ((size_t)b*TAz + t)*Lz;
  size_t e = (size_t)row*Lz;
  for (int i = tid; i < Lz; i += 256) dst[Dz+i] = qm[q+i] + qs[q+i]*eps[e+i];
}

// ---------------- y = gelu_out @ w2h + c2 ----------------
__global__ __launch_bounds__(256) void y_kernel(const float* __restrict__ gel,
                                                float* __restrict__ out_y)
{
  __shared__ float sw[Dz];
  __shared__ float c2s;
  int tid = threadIdx.x;
  for (int i = tid; i < Dz; i += 256) sw[i] = g_w2h[i];
  if (tid == 0) c2s = g_w2h[Dz];
  __syncthreads();
  int lane = tid & 31;
  int warp = (blockIdx.x*blockDim.x + tid) >> 5;
  int nwarp = (gridDim.x*blockDim.x) >> 5;
  for (int row = warp; row < Bz*THz; row += nwarp){
    const float* g = gel + (size_t)row*Dz;
    float s = 0.f;
    #pragma unroll
    for (int i = 0; i < Dz/32; i++) s += g[lane + i*32]*sw[lane + i*32];
    #pragma unroll
    for (int o = 16; o; o >>= 1) s += __shfl_xor_sync(0xffffffffu, s, o);
    if (lane == 0) out_y[row] = s + c2s;
  }
}

// ---------------- launch ----------------
extern "C" void kernel_launch(void* const* d_in, const int* in_sizes, int n_in,
                              void* d_out, int out_size)
{
  (void)in_sizes; (void)n_in; (void)out_size;
  const float* patches_hist = (const float*)d_in[0];
  const float* patches_all  = (const float*)d_in[1];
  const float* eps    = (const float*)d_in[2];
  const float* W_embed= (const float*)d_in[3];
  const float* b_embed= (const float*)d_in[4];
  const float* Wih_f  = (const float*)d_in[5];
  const float* Whh_f  = (const float*)d_in[6];
  const float* bih_f  = (const float*)d_in[7];
  const float* bhh_f  = (const float*)d_in[8];
  const float* Wih_b  = (const float*)d_in[9];
  const float* Whh_b  = (const float*)d_in[10];
  const float* bih_b  = (const float*)d_in[11];
  const float* bhh_b  = (const float*)d_in[12];
  const float* Wqm    = (const float*)d_in[13];
  const float* bqm    = (const float*)d_in[14];
  const float* Wqs    = (const float*)d_in[15];
  const float* bqs    = (const float*)d_in[16];
  const float* Wih_g  = (const float*)d_in[17];
  const float* Whh_g  = (const float*)d_in[18];
  const float* bih_g  = (const float*)d_in[19];
  const float* bhh_g  = (const float*)d_in[20];
  const float* Wpm    = (const float*)d_in[21];
  const float* bpm    = (const float*)d_in[22];
  const float* Wps    = (const float*)d_in[23];
  const float* bps    = (const float*)d_in[24];
  const float* W_e1   = (const float*)d_in[25];
  const float* b_e1   = (const float*)d_in[26];
  const float* W_e2   = (const float*)d_in[27];
  const float* b_e2   = (const float*)d_in[28];
  const float* W_head = (const float*)d_in[29];
  const float* b_head = (const float*)d_in[30];
  float* out = (float*)d_out;

  // output layout: y_hist, prior_m, prior_s, qm_all, qs_all, h_seq (flattened, concatenated)
  float* out_y  = out + 0;
  float* out_pm = out + 131072;
  float* out_ps = out + 16908288;
  float* out_qm = out + 33685504;
  float* out_qs = out + 52559872;
  float* out_h  = out + 71434240;

  float *x_hist, *x_all, *xgf, *xgb, *xgg, *hbi;
  cudaGetSymbolAddress((void**)&x_hist, g_x_hist);
  cudaGetSymbolAddress((void**)&x_all,  g_x_all);
  cudaGetSymbolAddress((void**)&xgf,    g_xgf);
  cudaGetSymbolAddress((void**)&xgb,    g_xgb);
  cudaGetSymbolAddress((void**)&xgg,    g_xgg);
  cudaGetSymbolAddress((void**)&hbi,    g_hbi);
  float* cat = xgf;     // reuse: xgf dead after LSTM steps
  float* gel = x_all;   // reuse: x_all dead after xg GEMMs

  const int LSTM_SMEM = (256*LSW + 32*LSH)*4;   // 172,544 B
  const int GRU_SMEM  = (512*GSW + 32*GSH)*4;   // 229,888 B
  static int attr_done = 0;
  if (!attr_done){
    cudaFuncSetAttribute(lstm_kernel,  cudaFuncAttributeMaxDynamicSharedMemorySize, LSTM_SMEM);
    cudaFuncSetAttribute(gru_kernel,   cudaFuncAttributeMaxDynamicSharedMemorySize, GRU_SMEM);
    cudaFuncSetAttribute(tgemm_kernel, cudaFuncAttributeMaxDynamicSharedMemorySize, TG_SMEM);
    attr_done = 1;
  }

  // 1. embed
  embed_kernel<<<(Bz*TAz)/64, 256>>>(patches_all,  W_embed, b_embed, x_all);
  embed_kernel<<<(Bz*THz)/64, 256>>>(patches_hist, W_embed, b_embed, x_hist);

  // 2. input-gate GEMMs (tf32 mma.sync, cp.async pipelined)
  tgemm_kernel<<<dim3(1024/128, (Bz*TAz)/128), 256, TG_SMEM>>>(x_all,  Wih_f, bih_f, xgf, Bz*TAz, 1024, 512, 0);
  tgemm_kernel<<<dim3(1024/128, (Bz*TAz)/128), 256, TG_SMEM>>>(x_all,  Wih_b, bih_b, xgb, Bz*TAz, 1024, 512, 0);
  tgemm_kernel<<<dim3(1536/128, (Bz*THz)/128), 256, TG_SMEM>>>(x_hist, Wih_g, bih_g, xgg, Bz*THz, 1536, 512, 0);

  // 3. recurrences: persistent tensor-core kernels, group-local barriers
  reset_bar_kernel<<<1,32>>>();
  lstm_kernel<<<128,256,LSTM_SMEM>>>(xgf, xgb, Whh_f, Whh_b, bhh_f, bhh_b, hbi);
  reset_bar_kernel<<<1,32>>>();
  gru_kernel<<<128,256,GRU_SMEM>>>(xgg, Whh_g, bhh_g, out_h);

  // 4. posterior / prior heads (tf32 mma.sync)
  tgemm_kernel<<<dim3(1, (Bz*TAz)/128), 256, TG_SMEM>>>(hbi,   Wqm, bqm, out_qm, Bz*TAz, 128, 512, 0);
  tgemm_kernel<<<dim3(1, (Bz*TAz)/128), 256, TG_SMEM>>>(hbi,   Wqs, bqs, out_qs, Bz*TAz, 128, 512, 1);
  tgemm_kernel<<<dim3(1, (Bz*THz)/128), 256, TG_SMEM>>>(out_h, Wpm, bpm, out_pm, Bz*THz, 128, 512, 0);
  tgemm_kernel<<<dim3(1, (Bz*THz)/128), 256, TG_SMEM>>>(out_h, Wps, bps, out_ps, Bz*THz, 128, 512, 1);

  // 5. emission (head folded: y = gelu(cat@W_e1+b_e1) @ (W_e2@W_head) + (b_e2@W_head + b_head))
  w2h_kernel<<<1,256>>>(W_e2, b_e2, W_head, b_head);
  cat_kernel<<<Bz*THz, 256>>>(out_h, out_qm, out_qs, eps, cat);
  tgemm_kernel<<<dim3(512/128, (Bz*THz)/128), 256, TG_SMEM>>>(cat, W_e1, b_e1, gel, Bz*THz, 512, 640, 2);
  y_kernel<<<2048,256>>>(gel, out_y);
}